// round 6
// baseline (speedup 1.0000x reference)
#include <cuda_runtime.h>
#include <cstdint>

#define BB 16
#define NN 4096
#define DD 256
#define BN_TOT (BB*NN)          // 65536
#define EPSF 1e-6f

// ---------------- scratch ----------------
__device__ float g_phiq[BN_TOT*DD];       // [bn][d] 64MB
__device__ float g_phik[BN_TOT*DD];       // [bn][d] 64MB
__device__ float g_rowsum[BN_TOT];
__device__ float g_colpart2[BB*32*DD];    // per-(b, m-tile) column partials
__device__ float g_colsum[BB*DD];
__device__ float g_psum[BB*DD*4];         // sum-exp partials (4 n-chunks)
__device__ float g_sinv[BB*DD];
__device__ float g_kvpart[4*BB*DD*DD];
__device__ float g_kv[BB*DD*DD];

__device__ __forceinline__ float sigf(float x){ return 1.0f/(1.0f + __expf(-x)); }
__device__ __forceinline__ float t32(float a){
    uint32_t u; asm("cvt.rna.tf32.f32 %0, %1;" : "=r"(u) : "f"(a)); return __uint_as_float(u);
}
__device__ __forceinline__ void mma8(float* d, const uint32_t* a, const uint32_t* b){
    asm volatile("mma.sync.aligned.m16n8k8.row.col.f32.tf32.tf32.f32 "
        "{%0,%1,%2,%3}, {%4,%5,%6,%7}, {%8,%9}, {%0,%1,%2,%3};"
        : "+f"(d[0]), "+f"(d[1]), "+f"(d[2]), "+f"(d[3])
        : "r"(a[0]), "r"(a[1]), "r"(a[2]), "r"(a[3]), "r"(b[0]), "r"(b[1]));
}

// ---------------- tf32 warp-mma GEMM core, 512 threads ----------------
// CTA tile 128(M) x 256(N), BK=32. Warps 4(M) x 4(N), warp tile 32x64.
// AMODE 0: A is [m][k]; AMODE 1: A memory is [k][m] (logical transpose).
// B is [k][n]. acc[mf 2][nf 8][4].
#define PA0 36
#define PA1 136
#define PBW 264
#define ASZ_B 18432                    // max(128*PA0, 32*PA1)*4
#define SMEM_GEMM (ASZ_B + 32*PBW*4)   // 52224

template<int AMODE>
__device__ __forceinline__ void gemm_core512(const float* __restrict__ A, int lda,
                                             const float* __restrict__ B, int ldb,
                                             int kchunks, float acc[2][8][4],
                                             float* As, float* Bs){
    const int tid = threadIdx.x;
    const int lane = tid & 31;
    const int wid = tid >> 5;
    const int wm = wid & 3, wn = wid >> 2;
    const int g = lane >> 2, c4 = lane & 3;

    #pragma unroll
    for (int mf = 0; mf < 2; mf++)
        #pragma unroll
        for (int nf = 0; nf < 8; nf++)
            #pragma unroll
            for (int j = 0; j < 4; j++) acc[mf][nf][j] = 0.f;

    for (int ch = 0; ch < kchunks; ch++){
        // stage A: 128x32 (1024 float4)
        if (AMODE == 0){
            #pragma unroll
            for (int i = 0; i < 2; i++){
                int idx = tid + i*512;
                int m = idx >> 3, kq = idx & 7;
                float4 v = *reinterpret_cast<const float4*>(A + (size_t)m*lda + ch*32 + kq*4);
                v.x=t32(v.x); v.y=t32(v.y); v.z=t32(v.z); v.w=t32(v.w);
                *reinterpret_cast<float4*>(As + m*PA0 + kq*4) = v;
            }
        } else {
            #pragma unroll
            for (int i = 0; i < 2; i++){
                int idx = tid + i*512;
                int kr = idx >> 5, mq = idx & 31;
                float4 v = *reinterpret_cast<const float4*>(A + (size_t)(ch*32 + kr)*lda + mq*4);
                v.x=t32(v.x); v.y=t32(v.y); v.z=t32(v.z); v.w=t32(v.w);
                *reinterpret_cast<float4*>(As + kr*PA1 + mq*4) = v;
            }
        }
        // stage B: 32x256 (2048 float4)
        #pragma unroll
        for (int i = 0; i < 4; i++){
            int idx = tid + i*512;
            int kr = idx >> 6, nq = idx & 63;
            float4 v = *reinterpret_cast<const float4*>(B + (size_t)(ch*32 + kr)*ldb + nq*4);
            v.x=t32(v.x); v.y=t32(v.y); v.z=t32(v.z); v.w=t32(v.w);
            *reinterpret_cast<float4*>(Bs + kr*PBW + nq*4) = v;
        }
        __syncthreads();

        #pragma unroll
        for (int ks = 0; ks < 4; ks++){
            const int kb = ks*8;
            uint32_t a[2][4], bf[8][2];
            #pragma unroll
            for (int mf = 0; mf < 2; mf++){
                int row = wm*32 + mf*16 + g;
                if (AMODE == 0){
                    a[mf][0] = __float_as_uint(As[(row  )*PA0 + kb + c4    ]);
                    a[mf][1] = __float_as_uint(As[(row+8)*PA0 + kb + c4    ]);
                    a[mf][2] = __float_as_uint(As[(row  )*PA0 + kb + c4 + 4]);
                    a[mf][3] = __float_as_uint(As[(row+8)*PA0 + kb + c4 + 4]);
                } else {
                    a[mf][0] = __float_as_uint(As[(kb+c4  )*PA1 + row    ]);
                    a[mf][1] = __float_as_uint(As[(kb+c4  )*PA1 + row + 8]);
                    a[mf][2] = __float_as_uint(As[(kb+c4+4)*PA1 + row    ]);
                    a[mf][3] = __float_as_uint(As[(kb+c4+4)*PA1 + row + 8]);
                }
            }
            #pragma unroll
            for (int nf = 0; nf < 8; nf++){
                int ncol = wn*64 + nf*8 + g;
                bf[nf][0] = __float_as_uint(Bs[(kb+c4  )*PBW + ncol]);
                bf[nf][1] = __float_as_uint(Bs[(kb+c4+4)*PBW + ncol]);
            }
            #pragma unroll
            for (int mf = 0; mf < 2; mf++)
                #pragma unroll
                for (int nf = 0; nf < 8; nf++)
                    mma8(acc[mf][nf], a[mf], bf[nf]);
        }
        __syncthreads();
    }
}

// ================= GEMM kernels =================
// phi = sigmoid(X @ W + b), full-width 256-N tile, fused rowsum (q) / colsum partials (k)
__global__ __launch_bounds__(512, 1) void k_phi(const float* __restrict__ X,
                                                const float* __restrict__ W,
                                                const float* __restrict__ bias, int which){
    extern __shared__ float sm[];
    float* As = sm;
    float* Bs = sm + ASZ_B/4;
    float* out = which ? g_phik : g_phiq;
    const int m0 = blockIdx.x * 128;
    float acc[2][8][4];
    gemm_core512<0>(X + (size_t)m0*DD, DD, W, DD, 8, acc, As, Bs);

    const int tid = threadIdx.x, lane = tid & 31, wid = tid >> 5;
    const int wm = wid & 3, wn = wid >> 2, g = lane >> 2, c4 = lane & 3;

    float rpart[2][2];   // [mf][row half] row-sum partials (phi_q)
    float cpart[8][2];   // [nf][col pair] col-sum partials (phi_k)
    #pragma unroll
    for (int mf = 0; mf < 2; mf++){ rpart[mf][0]=0.f; rpart[mf][1]=0.f; }
    #pragma unroll
    for (int nf = 0; nf < 8; nf++){ cpart[nf][0]=0.f; cpart[nf][1]=0.f; }

    #pragma unroll
    for (int mf = 0; mf < 2; mf++){
        int row = m0 + wm*32 + mf*16 + g;
        #pragma unroll
        for (int nf = 0; nf < 8; nf++){
            int col = wn*64 + nf*8 + c4*2;
            float b0 = bias[col], b1 = bias[col+1];
            float2 r0 = { sigf(acc[mf][nf][0] + b0), sigf(acc[mf][nf][1] + b1) };
            float2 r1 = { sigf(acc[mf][nf][2] + b0), sigf(acc[mf][nf][3] + b1) };
            *reinterpret_cast<float2*>(out + (size_t)row*DD + col)     = r0;
            *reinterpret_cast<float2*>(out + (size_t)(row+8)*DD + col) = r1;
            rpart[mf][0] += r0.x + r0.y;
            rpart[mf][1] += r1.x + r1.y;
            cpart[nf][0] += r0.x + r1.x;
            cpart[nf][1] += r0.y + r1.y;
        }
    }
    __syncthreads();   // staging no longer needed; reuse As for reductions

    if (!which){
        // rowsum: reduce over c4 (lanes 1,2), stash per-wn, combine
        #pragma unroll
        for (int mf = 0; mf < 2; mf++)
            #pragma unroll
            for (int h = 0; h < 2; h++){
                rpart[mf][h] += __shfl_xor_sync(0xffffffffu, rpart[mf][h], 1);
                rpart[mf][h] += __shfl_xor_sync(0xffffffffu, rpart[mf][h], 2);
            }
        if (c4 == 0){
            #pragma unroll
            for (int mf = 0; mf < 2; mf++){
                int r = wm*32 + mf*16 + g;
                As[wn*128 + r]     = rpart[mf][0];
                As[wn*128 + r + 8] = rpart[mf][1];
            }
        }
        __syncthreads();
        if (tid < 128){
            float s = ((As[tid] + As[128+tid]) + (As[256+tid] + As[384+tid]));
            g_rowsum[m0 + tid] = s;
        }
    } else {
        // colsum partials: reduce over g (lane bits 2..4), stash per-wm, combine
        #pragma unroll
        for (int nf = 0; nf < 8; nf++)
            #pragma unroll
            for (int h = 0; h < 2; h++){
                cpart[nf][h] += __shfl_xor_sync(0xffffffffu, cpart[nf][h], 4);
                cpart[nf][h] += __shfl_xor_sync(0xffffffffu, cpart[nf][h], 8);
                cpart[nf][h] += __shfl_xor_sync(0xffffffffu, cpart[nf][h], 16);
            }
        if (g == 0){
            #pragma unroll
            for (int nf = 0; nf < 8; nf++){
                int col = wn*64 + nf*8 + c4*2;
                As[wm*256 + col]     = cpart[nf][0];
                As[wm*256 + col + 1] = cpart[nf][1];
            }
        }
        __syncthreads();
        if (tid < 256){
            float s = ((As[tid] + As[256+tid]) + (As[512+tid] + As[768+tid]));
            int b = m0 >> 12, mt = (m0 >> 7) & 31;
            g_colpart2[((b*32 + mt) << 8) + tid] = s;
        }
    }
}

// KV partials: KV[b] = phi_k[b]^T @ V_b[b]; split-K x4, full-width N=256
__global__ __launch_bounds__(512, 1) void k_kv(const float* __restrict__ vb){
    extern __shared__ float sm[];
    float* As = sm;
    float* Bs = sm + ASZ_B/4;
    const int d0 = blockIdx.x * 128, ks = blockIdx.y, b = blockIdx.z;
    const float* A  = g_phik + (size_t)(b*NN + ks*1024)*DD + d0;   // [k=n][m=d]
    const float* Bv = vb     + (size_t)(b*NN + ks*1024)*DD;        // [k=n][n=e]
    float acc[2][8][4];
    gemm_core512<1>(A, DD, Bv, DD, 32, acc, As, Bs);

    const int tid = threadIdx.x, lane = tid & 31, wid = tid >> 5;
    const int wm = wid & 3, wn = wid >> 2, g = lane >> 2, c4 = lane & 3;
    float* part = g_kvpart + (size_t)(ks*BB + b)*DD*DD;
    #pragma unroll
    for (int mf = 0; mf < 2; mf++){
        int row = d0 + wm*32 + mf*16 + g;
        #pragma unroll
        for (int nf = 0; nf < 8; nf++){
            int col = wn*64 + nf*8 + c4*2;
            float2 r0 = { acc[mf][nf][0], acc[mf][nf][1] };
            float2 r1 = { acc[mf][nf][2], acc[mf][nf][3] };
            *reinterpret_cast<float2*>(part + (size_t)row*DD + col)     = r0;
            *reinterpret_cast<float2*>(part + (size_t)(row+8)*DD + col) = r1;
        }
    }
}

// R = gate(rowsum) * (phi_q @ KV[b]); full-width N=256
__global__ __launch_bounds__(512, 1) void k_out(float* __restrict__ out){
    extern __shared__ float sm[];
    float* As = sm;
    float* Bs = sm + ASZ_B/4;
    const int m0 = blockIdx.x * 128;
    const int b = m0 >> 12;
    float acc[2][8][4];
    gemm_core512<0>(g_phiq + (size_t)m0*DD, DD, g_kv + (size_t)b*DD*DD, DD, 8, acc, As, Bs);

    const int tid = threadIdx.x, lane = tid & 31, wid = tid >> 5;
    const int wm = wid & 3, wn = wid >> 2, g = lane >> 2, c4 = lane & 3;
    #pragma unroll
    for (int mf = 0; mf < 2; mf++){
        int row = m0 + wm*32 + mf*16 + g;
        float rs0 = g_rowsum[row],   sc0 = sigf(rs0) / (rs0 + EPSF);
        float rs1 = g_rowsum[row+8], sc1 = sigf(rs1) / (rs1 + EPSF);
        #pragma unroll
        for (int nf = 0; nf < 8; nf++){
            int col = wn*64 + nf*8 + c4*2;
            float2 r0 = { acc[mf][nf][0]*sc0, acc[mf][nf][1]*sc0 };
            float2 r1 = { acc[mf][nf][2]*sc1, acc[mf][nf][3]*sc1 };
            *reinterpret_cast<float2*>(out + (size_t)row*DD + col)     = r0;
            *reinterpret_cast<float2*>(out + (size_t)(row+8)*DD + col) = r1;
        }
    }
}

// ================= small kernels =================
__global__ __launch_bounds__(256) void k_colsum(){
    int idx = blockIdx.x*256 + threadIdx.x;       // b*DD + d
    int b = idx >> 8, d = idx & 255;
    float s = 0.f;
    #pragma unroll
    for (int mt = 0; mt < 32; mt++) s += g_colpart2[((b*32+mt)<<8) + d];
    g_colsum[idx] = s;
}

// sum-of-exp partials (no max needed: |s| << 1)
__global__ __launch_bounds__(256) void k_sumexp(const float* __restrict__ V){
    int nc = blockIdx.x, dc = blockIdx.y, b = blockIdx.z;
    int tid = threadIdx.x;
    int dl = tid & 31, ng = tid >> 5;
    int d = dc*32 + dl;
    float c = 1.0f/(g_colsum[b*DD + d] + EPSF);
    int n0 = nc*1024;
    const float* pk = g_phik + (size_t)(b*NN + n0)*DD + d;
    const float* pv = V      + (size_t)(b*NN + n0)*DD + d;
    float z = 0.f;
    #pragma unroll 4
    for (int i = ng; i < 1024; i += 8)
        z += __expf((pk[(size_t)i*DD]*pv[(size_t)i*DD])*c);
    __shared__ float sh[256];
    sh[tid] = z; __syncthreads();
    if (tid < 32){
        float Z = 0.f;
        #pragma unroll
        for (int k = 0; k < 8; k++) Z += sh[k*32 + tid];
        g_psum[(b*DD + d)*4 + nc] = Z;
    }
}

__global__ __launch_bounds__(256) void k_sinv(){
    int idx = blockIdx.x*256 + threadIdx.x;       // 4096 columns
    float Z = ((g_psum[idx*4] + g_psum[idx*4+1]) + (g_psum[idx*4+2] + g_psum[idx*4+3]));
    g_sinv[idx] = 1.0f/Z;
}

__global__ __launch_bounds__(256) void k_writevb(const float* __restrict__ V, float* __restrict__ vb){
    int i4 = blockIdx.x*256 + threadIdx.x;
    size_t base = (size_t)i4*4;
    int d0 = (int)(base & 255);
    int bn = (int)(base >> 8);
    int b  = bn >> 12;
    int cb = b*DD + d0;
    float4 pk = *reinterpret_cast<const float4*>(&g_phik[base]);
    float4 vv = *reinterpret_cast<const float4*>(&V[base]);
    float pks[4]={pk.x,pk.y,pk.z,pk.w};
    float vvs[4]={vv.x,vv.y,vv.z,vv.w};
    float o[4];
    #pragma unroll
    for (int j=0;j<4;j++){
        float c = 1.0f/(g_colsum[cb+j] + EPSF);
        o[j] = __expf((pks[j]*vvs[j])*c) * g_sinv[cb+j];
    }
    float4 r = {o[0],o[1],o[2],o[3]};
    *reinterpret_cast<float4*>(&vb[base]) = r;
}

__global__ __launch_bounds__(256) void k_kvsum(){
    int idx = blockIdx.x*256 + threadIdx.x;
    const int S = BB*DD*DD;
    g_kv[idx] = ((g_kvpart[idx] + g_kvpart[idx+S]) + (g_kvpart[idx+2*S] + g_kvpart[idx+3*S]));
}

// ================= launch =================
extern "C" void kernel_launch(void* const* d_in, const int* in_sizes, int n_in,
                              void* d_out, int out_size){
    const float* Q  = (const float*)d_in[0];
    const float* K  = (const float*)d_in[1];
    const float* V  = (const float*)d_in[2];
    const float* Wq = (const float*)d_in[3];
    const float* bq = (const float*)d_in[4];
    const float* Wk = (const float*)d_in[5];
    const float* bk = (const float*)d_in[6];
    float* out = (float*)d_out;
    (void)in_sizes; (void)n_in; (void)out_size;

    cudaFuncSetAttribute(k_phi, cudaFuncAttributeMaxDynamicSharedMemorySize, SMEM_GEMM);
    cudaFuncSetAttribute(k_kv,  cudaFuncAttributeMaxDynamicSharedMemorySize, SMEM_GEMM);
    cudaFuncSetAttribute(k_out, cudaFuncAttributeMaxDynamicSharedMemorySize, SMEM_GEMM);

    k_phi<<<512, 512, SMEM_GEMM>>>(Q, Wq, bq, 0);   // phi_q + rowsum
    k_phi<<<512, 512, SMEM_GEMM>>>(K, Wk, bk, 1);   // phi_k + colsum partials
    k_colsum<<<16, 256>>>();
    k_sumexp<<<dim3(4, 8, BB), 256>>>(V);
    k_sinv<<<16, 256>>>();
    k_writevb<<<(BN_TOT*DD/4)/256, 256>>>(V, out);  // V_b -> d_out scratch
    k_kv<<<dim3(2, 4, BB), 512, SMEM_GEMM>>>(out);  // split-K KV partials
    k_kvsum<<<BB*DD*DD/256, 256>>>();
    k_out<<<512, 512, SMEM_GEMM>>>(out);            // final R
}

// round 9
// speedup vs baseline: 1.2668x; 1.2668x over previous
#include <cuda_runtime.h>
#include <cstdint>

#define BB 16
#define NN 4096
#define DD 256
#define BN_TOT (BB*NN)          // 65536
#define EPSF 1e-6f

// ---------------- scratch ----------------
__device__ float g_phiq[BN_TOT*DD];       // [bn][d] 64MB (tf32-rounded)
__device__ float g_phik[BN_TOT*DD];       // [bn][d] 64MB (tf32-rounded)
__device__ float g_rowpart[2*BN_TOT];     // row-sum partials per e-tile
__device__ float g_colpart2[BB*32*DD];    // col-sum partials per (b, m-tile)
__device__ float g_colsum[BB*DD];
__device__ float g_zpart[BB*4*DD];        // softmax-denominator partials per ks
__device__ float g_kvpart[4*BB*DD*DD];    // split-K KV partials
__device__ float g_kv[BB*DD*DD];          // (tf32-rounded)

__device__ __forceinline__ float sigf(float x){ return 1.0f/(1.0f + __expf(-x)); }
__device__ __forceinline__ float t32(float a){
    uint32_t u; asm("cvt.rna.tf32.f32 %0, %1;" : "=r"(u) : "f"(a)); return __uint_as_float(u);
}
__device__ __forceinline__ void mma8(float* d, const uint32_t* a, const uint32_t* b){
    asm volatile("mma.sync.aligned.m16n8k8.row.col.f32.tf32.tf32.f32 "
        "{%0,%1,%2,%3}, {%4,%5,%6,%7}, {%8,%9}, {%0,%1,%2,%3};"
        : "+f"(d[0]), "+f"(d[1]), "+f"(d[2]), "+f"(d[3])
        : "r"(a[0]), "r"(a[1]), "r"(a[2]), "r"(a[3]), "r"(b[0]), "r"(b[1]));
}
__device__ __forceinline__ uint32_t smem_u32(const void* p){
    uint32_t a; asm("{ .reg .u64 t; cvta.to.shared.u64 t, %1; cvt.u32.u64 %0, t; }" : "=r"(a) : "l"(p));
    return a;
}
__device__ __forceinline__ void cpa16(uint32_t saddr, const float* g){
    asm volatile("cp.async.ca.shared.global [%0], [%1], 16;" :: "r"(saddr), "l"(g));
}
#define CP_COMMIT() asm volatile("cp.async.commit_group;" ::: "memory")
#define CP_WAIT1()  asm volatile("cp.async.wait_group 1;" ::: "memory")
#define CP_WAIT0()  asm volatile("cp.async.wait_group 0;" ::: "memory")

// ---------------- tile geometry (256 thr, 128x128, BK=32) ----------------
#define PA0 36
#define PA1 136
#define PB  136
#define A_FL (128*PA0)     // 4608 floats
#define B_FL (32*PB)       // 4352 floats
#define STAGE_FL (A_FL + B_FL)          // 8960
#define SMEM_DB (2*STAGE_FL*4)          // 71680 bytes

// fragment math on one staged chunk (AMODE 0: A [m][k])
__device__ __forceinline__ void math_chunk0(const float* As, const float* Bs, float acc[2][8][4],
                                            int wm, int wn, int g, int c4){
    #pragma unroll
    for (int ks = 0; ks < 4; ks++){
        const int kb = ks*8;
        uint32_t a[2][4], bf[8][2];
        #pragma unroll
        for (int mf = 0; mf < 2; mf++){
            int row = wm*32 + mf*16 + g;
            a[mf][0] = __float_as_uint(As[(row  )*PA0 + kb + c4    ]);
            a[mf][1] = __float_as_uint(As[(row+8)*PA0 + kb + c4    ]);
            a[mf][2] = __float_as_uint(As[(row  )*PA0 + kb + c4 + 4]);
            a[mf][3] = __float_as_uint(As[(row+8)*PA0 + kb + c4 + 4]);
        }
        #pragma unroll
        for (int nf = 0; nf < 8; nf++){
            int ncol = wn*64 + nf*8 + g;
            bf[nf][0] = __float_as_uint(Bs[(kb+c4  )*PB + ncol]);
            bf[nf][1] = __float_as_uint(Bs[(kb+c4+4)*PB + ncol]);
        }
        #pragma unroll
        for (int mf = 0; mf < 2; mf++)
            #pragma unroll
            for (int nf = 0; nf < 8; nf++)
                mma8(acc[mf][nf], a[mf], bf[nf]);
    }
}

// async stage of one chunk (raw bytes, no cvt) into stage buffer s
__device__ __forceinline__ void stage_async(uint32_t su, int s, const float* A, int lda,
                                            const float* B, int ldb, int ch, int tid){
    uint32_t base = su + (uint32_t)(s*STAGE_FL*4);
    #pragma unroll
    for (int i = 0; i < 4; i++){
        int idx = tid + i*256;           // A: 1024 float4 (128m x 8kq)
        int m = idx >> 3, kq = idx & 7;
        cpa16(base + (uint32_t)(m*PA0 + kq*4)*4, A + (size_t)m*lda + ch*32 + kq*4);
    }
    uint32_t bbase = base + A_FL*4;
    #pragma unroll
    for (int i = 0; i < 4; i++){
        int idx = tid + i*256;           // B: 1024 float4 (32k x 32nq)
        int kr = idx >> 5, nq = idx & 31;
        cpa16(bbase + (uint32_t)(kr*PB + nq*4)*4, B + (size_t)(ch*32 + kr)*ldb + nq*4);
    }
}

// in-place RNA tf32 convert of the bytes THIS thread staged (own-data, pre-sync ok)
__device__ __forceinline__ void convert_stage(float* sm, int s, int tid){
    float* base = sm + s*STAGE_FL;
    #pragma unroll
    for (int i = 0; i < 4; i++){
        int idx = tid + i*256;
        int m = idx >> 3, kq = idx & 7;
        float4* p = reinterpret_cast<float4*>(base + m*PA0 + kq*4);
        float4 v = *p;
        v.x=t32(v.x); v.y=t32(v.y); v.z=t32(v.z); v.w=t32(v.w);
        *p = v;
    }
    float* bb = base + A_FL;
    #pragma unroll
    for (int i = 0; i < 4; i++){
        int idx = tid + i*256;
        int kr = idx >> 5, nq = idx & 31;
        float4* p = reinterpret_cast<float4*>(bb + kr*PB + nq*4);
        float4 v = *p;
        v.x=t32(v.x); v.y=t32(v.y); v.z=t32(v.z); v.w=t32(v.w);
        *p = v;
    }
}

// double-buffered async GEMM mainloop. CVT=1: raw fp32 inputs (convert in place).
template<int CVT>
__device__ __forceinline__ void gemm_async(const float* A, int lda, const float* B, int ldb,
                                           int kchunks, float acc[2][8][4], float* sm, uint32_t su){
    const int tid = threadIdx.x, lane = tid & 31, wid = tid >> 5;
    const int wm = wid & 3, wn = wid >> 2, g = lane >> 2, c4 = lane & 3;
    #pragma unroll
    for (int mf = 0; mf < 2; mf++)
        #pragma unroll
        for (int nf = 0; nf < 8; nf++)
            #pragma unroll
            for (int j = 0; j < 4; j++) acc[mf][nf][j] = 0.f;

    stage_async(su, 0, A, lda, B, ldb, 0, tid);
    CP_COMMIT();
    for (int ch = 0; ch < kchunks; ch++){
        int cur = ch & 1;
        if (ch + 1 < kchunks){
            stage_async(su, cur ^ 1, A, lda, B, ldb, ch + 1, tid);
            CP_COMMIT();
            CP_WAIT1();
        } else {
            CP_WAIT0();
        }
        if (CVT) convert_stage(sm, cur, tid);
        __syncthreads();
        math_chunk0(sm + cur*STAGE_FL, sm + cur*STAGE_FL + A_FL, acc, wm, wn, g, c4);
        __syncthreads();
    }
}

// ================= k_phi: phi = sigmoid(X @ W + b) + fused reductions =================
__global__ __launch_bounds__(256, 2) void k_phi(const float* __restrict__ X,
                                                const float* __restrict__ W,
                                                const float* __restrict__ bias, int which){
    extern __shared__ float sm[];
    uint32_t su = smem_u32(sm);
    float* out = which ? g_phik : g_phiq;
    const int m0 = blockIdx.y * 128, e0 = blockIdx.x * 128;
    float acc[2][8][4];
    gemm_async<1>(X + (size_t)m0*DD, DD, W + e0, DD, 8, acc, sm, su);

    const int tid = threadIdx.x, lane = tid & 31, wid = tid >> 5;
    const int wm = wid & 3, wn = wid >> 2, g = lane >> 2, c4 = lane & 3;

    float rpart[2][2] = {{0.f,0.f},{0.f,0.f}};
    float cpart[8][2];
    #pragma unroll
    for (int nf = 0; nf < 8; nf++){ cpart[nf][0]=0.f; cpart[nf][1]=0.f; }

    #pragma unroll
    for (int mf = 0; mf < 2; mf++){
        int row = m0 + wm*32 + mf*16 + g;
        #pragma unroll
        for (int nf = 0; nf < 8; nf++){
            int lcol = wn*64 + nf*8 + c4*2;
            float b0 = bias[e0 + lcol], b1 = bias[e0 + lcol + 1];
            float s00 = sigf(acc[mf][nf][0] + b0), s01 = sigf(acc[mf][nf][1] + b1);
            float s10 = sigf(acc[mf][nf][2] + b0), s11 = sigf(acc[mf][nf][3] + b1);
            float2 r0 = { t32(s00), t32(s01) };
            float2 r1 = { t32(s10), t32(s11) };
            *reinterpret_cast<float2*>(out + (size_t)row*DD + e0 + lcol)     = r0;
            *reinterpret_cast<float2*>(out + (size_t)(row+8)*DD + e0 + lcol) = r1;
            rpart[mf][0] += s00 + s01;
            rpart[mf][1] += s10 + s11;
            cpart[nf][0] += s00 + s10;
            cpart[nf][1] += s01 + s11;
        }
    }
    __syncthreads();   // staging buffers free; reuse sm for reductions

    if (!which){
        #pragma unroll
        for (int mf = 0; mf < 2; mf++)
            #pragma unroll
            for (int h = 0; h < 2; h++){
                rpart[mf][h] += __shfl_xor_sync(0xffffffffu, rpart[mf][h], 1);
                rpart[mf][h] += __shfl_xor_sync(0xffffffffu, rpart[mf][h], 2);
            }
        if (c4 == 0){
            #pragma unroll
            for (int mf = 0; mf < 2; mf++){
                int r = wm*32 + mf*16 + g;
                sm[wn*128 + r]     = rpart[mf][0];
                sm[wn*128 + r + 8] = rpart[mf][1];
            }
        }
        __syncthreads();
        if (tid < 128)
            g_rowpart[(size_t)blockIdx.x*BN_TOT + m0 + tid] = sm[tid] + sm[128 + tid];
    } else {
        #pragma unroll
        for (int nf = 0; nf < 8; nf++)
            #pragma unroll
            for (int h = 0; h < 2; h++){
                cpart[nf][h] += __shfl_xor_sync(0xffffffffu, cpart[nf][h], 4);
                cpart[nf][h] += __shfl_xor_sync(0xffffffffu, cpart[nf][h], 8);
                cpart[nf][h] += __shfl_xor_sync(0xffffffffu, cpart[nf][h], 16);
            }
        if (g == 0){
            #pragma unroll
            for (int nf = 0; nf < 8; nf++){
                int lcol = wn*64 + nf*8 + c4*2;
                sm[wm*128 + lcol]     = cpart[nf][0];
                sm[wm*128 + lcol + 1] = cpart[nf][1];
            }
        }
        __syncthreads();
        if (tid < 128){
            float s = ((sm[tid] + sm[128+tid]) + (sm[256+tid] + sm[384+tid]));
            int b = m0 >> 12, mt = (m0 >> 7) & 31;
            g_colpart2[((b*32 + mt) << 8) + e0 + tid] = s;
        }
    }
}

// ================= k_colsum =================
__global__ __launch_bounds__(256) void k_colsum(){
    int idx = blockIdx.x*256 + threadIdx.x;       // b*DD + d
    int b = idx >> 8, d = idx & 255;
    float s = 0.f;
    #pragma unroll
    for (int mt = 0; mt < 32; mt++) s += g_colpart2[((b*32+mt)<<8) + d];
    g_colsum[idx] = s;
}

// ================= k_kv: KV' partials with inline exp-B + Z by-product =================
// grid (2 e-tiles, 2 d-tiles, BB*4 ks); A = phi_k[n][d-tile] (AMODE1), B = exp((phi_k*V)*c)
__global__ __launch_bounds__(256, 2) void k_kv(const float* __restrict__ V){
    __shared__ float As[32*PA1];
    __shared__ float Bs[32*PB];
    __shared__ float cinv[128];
    __shared__ float zsm[8*128];
    const int tid = threadIdx.x, lane = tid & 31, wid = tid >> 5;
    const int wm = wid & 3, wn = wid >> 2, g = lane >> 2, c4 = lane & 3;
    const int e0 = blockIdx.x * 128, d0 = blockIdx.y * 128;
    const int b = blockIdx.z >> 2, ks = blockIdx.z & 3;
    const float* A  = g_phik + (size_t)(b*NN + ks*1024)*DD + d0;
    const float* PK = g_phik + (size_t)(b*NN + ks*1024)*DD + e0;
    const float* PV = V      + (size_t)(b*NN + ks*1024)*DD + e0;

    if (tid < 128) cinv[tid] = 1.0f/(g_colsum[b*DD + e0 + tid] + EPSF);
    __syncthreads();

    float acc[2][8][4];
    #pragma unroll
    for (int mf = 0; mf < 2; mf++)
        #pragma unroll
        for (int nf = 0; nf < 8; nf++)
            #pragma unroll
            for (int j = 0; j < 4; j++) acc[mf][nf][j] = 0.f;

    const int nq = tid & 31;           // fixed per thread
    float z[4] = {0.f, 0.f, 0.f, 0.f};
    float cx = cinv[nq*4], cy = cinv[nq*4+1], cz = cinv[nq*4+2], cw = cinv[nq*4+3];

    for (int ch = 0; ch < 32; ch++){
        // A: phi_k pre-rounded tf32 — raw copy
        #pragma unroll
        for (int i = 0; i < 4; i++){
            int idx = tid + i*256;
            int kr = idx >> 5, mq = idx & 31;
            float4 v = *reinterpret_cast<const float4*>(A + (size_t)(ch*32 + kr)*DD + mq*4);
            *reinterpret_cast<float4*>(As + kr*PA1 + mq*4) = v;
        }
        // B: exp((pk*pv)*c), accumulate Z, store tf32-rounded
        #pragma unroll
        for (int i = 0; i < 4; i++){
            int idx = tid + i*256;
            int kr = idx >> 5;
            float4 a = *reinterpret_cast<const float4*>(PK + (size_t)(ch*32 + kr)*DD + nq*4);
            float4 v = *reinterpret_cast<const float4*>(PV + (size_t)(ch*32 + kr)*DD + nq*4);
            float ex = __expf(a.x*v.x*cx);
            float ey = __expf(a.y*v.y*cy);
            float ez = __expf(a.z*v.z*cz);
            float ew = __expf(a.w*v.w*cw);
            z[0] += ex; z[1] += ey; z[2] += ez; z[3] += ew;
            float4 r = { t32(ex), t32(ey), t32(ez), t32(ew) };
            *reinterpret_cast<float4*>(Bs + kr*PB + nq*4) = r;
        }
        __syncthreads();

        #pragma unroll
        for (int kss = 0; kss < 4; kss++){
            const int kb = kss*8;
            uint32_t a[2][4], bf[8][2];
            #pragma unroll
            for (int mf = 0; mf < 2; mf++){
                int row = wm*32 + mf*16 + g;
                a[mf][0] = __float_as_uint(As[(kb+c4  )*PA1 + row    ]);
                a[mf][1] = __float_as_uint(As[(kb+c4  )*PA1 + row + 8]);
                a[mf][2] = __float_as_uint(As[(kb+c4+4)*PA1 + row    ]);
                a[mf][3] = __float_as_uint(As[(kb+c4+4)*PA1 + row + 8]);
            }
            #pragma unroll
            for (int nf = 0; nf < 8; nf++){
                int ncol = wn*64 + nf*8 + g;
                bf[nf][0] = __float_as_uint(Bs[(kb+c4  )*PB + ncol]);
                bf[nf][1] = __float_as_uint(Bs[(kb+c4+4)*PB + ncol]);
            }
            #pragma unroll
            for (int mf = 0; mf < 2; mf++)
                #pragma unroll
                for (int nf = 0; nf < 8; nf++)
                    mma8(acc[mf][nf], a[mf], bf[nf]);
        }
        __syncthreads();
    }

    // Z partials (only d-tile 0 writes; deterministic fixed-order sums)
    #pragma unroll
    for (int j = 0; j < 4; j++) zsm[wid*128 + nq*4 + j] = z[j];
    __syncthreads();
    if (blockIdx.y == 0 && tid < 128){
        float Z = 0.f;
        #pragma unroll
        for (int w = 0; w < 8; w++) Z += zsm[w*128 + tid];
        g_zpart[(b*4 + ks)*DD + e0 + tid] = Z;
    }

    float* part = g_kvpart + (size_t)(ks*BB + b)*DD*DD;
    #pragma unroll
    for (int mf = 0; mf < 2; mf++){
        int row = d0 + wm*32 + mf*16 + g;
        #pragma unroll
        for (int nf = 0; nf < 8; nf++){
            int col = e0 + wn*64 + nf*8 + c4*2;
            float2 r0 = { acc[mf][nf][0], acc[mf][nf][1] };
            float2 r1 = { acc[mf][nf][2], acc[mf][nf][3] };
            *reinterpret_cast<float2*>(part + (size_t)row*DD + col)     = r0;
            *reinterpret_cast<float2*>(part + (size_t)(row+8)*DD + col) = r1;
        }
    }
}

// ================= k_kvscale: kv = (Σ ks parts) / Z[e], tf32-rounded =================
__global__ __launch_bounds__(256) void k_kvscale(){
    int idx = blockIdx.x*256 + threadIdx.x;       // b*DD*DD + d*DD + e
    const int S = BB*DD*DD;
    int e = idx & 255, b = idx >> 16;
    int zb = b*4*DD + e;
    float Z = ((g_zpart[zb] + g_zpart[zb+DD]) + (g_zpart[zb+2*DD] + g_zpart[zb+3*DD]));
    float v = ((g_kvpart[idx] + g_kvpart[idx+S]) + (g_kvpart[idx+2*S] + g_kvpart[idx+3*S]));
    g_kv[idx] = t32(v / Z);
}

// ================= k_out: R = gate(rowsum) * (phi_q @ KV[b]) =================
__global__ __launch_bounds__(256, 2) void k_out(float* __restrict__ out){
    extern __shared__ float sm[];
    uint32_t su = smem_u32(sm);
    const int m0 = blockIdx.y * 128, e0 = blockIdx.x * 128;
    const int b = m0 >> 12;
    float acc[2][8][4];
    gemm_async<0>(g_phiq + (size_t)m0*DD, DD, g_kv + (size_t)b*DD*DD + e0, DD, 8, acc, sm, su);

    const int tid = threadIdx.x, lane = tid & 31, wid = tid >> 5;
    const int wm = wid & 3, wn = wid >> 2, g = lane >> 2, c4 = lane & 3;
    #pragma unroll
    for (int mf = 0; mf < 2; mf++){
        int row = m0 + wm*32 + mf*16 + g;
        float rs0 = g_rowpart[row]   + g_rowpart[BN_TOT + row];
        float rs1 = g_rowpart[row+8] + g_rowpart[BN_TOT + row + 8];
        float sc0 = sigf(rs0) / (rs0 + EPSF);
        float sc1 = sigf(rs1) / (rs1 + EPSF);
        #pragma unroll
        for (int nf = 0; nf < 8; nf++){
            int col = e0 + wn*64 + nf*8 + c4*2;
            float2 r0 = { acc[mf][nf][0]*sc0, acc[mf][nf][1]*sc0 };
            float2 r1 = { acc[mf][nf][2]*sc1, acc[mf][nf][3]*sc1 };
            *reinterpret_cast<float2*>(out + (size_t)row*DD + col)     = r0;
            *reinterpret_cast<float2*>(out + (size_t)(row+8)*DD + col) = r1;
        }
    }
}

// ================= launch =================
extern "C" void kernel_launch(void* const* d_in, const int* in_sizes, int n_in,
                              void* d_out, int out_size){
    const float* Q  = (const float*)d_in[0];
    const float* K  = (const float*)d_in[1];
    const float* V  = (const float*)d_in[2];
    const float* Wq = (const float*)d_in[3];
    const float* bq = (const float*)d_in[4];
    const float* Wk = (const float*)d_in[5];
    const float* bk = (const float*)d_in[6];
    float* out = (float*)d_out;
    (void)in_sizes; (void)n_in; (void)out_size;

    cudaFuncSetAttribute(k_phi, cudaFuncAttributeMaxDynamicSharedMemorySize, SMEM_DB);
    cudaFuncSetAttribute(k_out, cudaFuncAttributeMaxDynamicSharedMemorySize, SMEM_DB);

    k_phi<<<dim3(2,512), 256, SMEM_DB>>>(Q, Wq, bq, 0);   // phi_q + rowsum partials
    k_phi<<<dim3(2,512), 256, SMEM_DB>>>(K, Wk, bk, 1);   // phi_k + colsum partials
    k_colsum<<<16, 256>>>();
    k_kv<<<dim3(2,2,BB*4), 256>>>(V);                     // KV' partials + Z
    k_kvscale<<<BB*DD*DD/256, 256>>>();
    k_out<<<dim3(2,512), 256, SMEM_DB>>>(out);            // final R
}

// round 10
// speedup vs baseline: 1.3220x; 1.0436x over previous
#include <cuda_runtime.h>
#include <cstdint>

#define BB 16
#define NN 4096
#define DD 256
#define BN_TOT (BB*NN)          // 65536
#define EPSF 1e-6f

// ---------------- scratch ----------------
__device__ float g_phiq[BN_TOT*DD];       // [bn][d] 64MB (tf32-rounded)
__device__ float g_phik[BN_TOT*DD];       // [bn][d] 64MB (tf32-rounded)
__device__ float g_rowpart[2*BN_TOT];     // row-sum partials per e-tile
__device__ float g_colpart2[BB*32*DD];    // col-sum partials per (b, m-tile)
__device__ float g_colsum[BB*DD];
__device__ float g_zpart[BB*2*DD];        // softmax-denominator partials per ks
__device__ float g_kvpart[2*BB*DD*DD];    // split-K KV partials
__device__ float g_kv[BB*DD*DD];          // (tf32-rounded)

__device__ __forceinline__ float sigf(float x){ return 1.0f/(1.0f + __expf(-x)); }
__device__ __forceinline__ float t32(float a){
    uint32_t u; asm("cvt.rna.tf32.f32 %0, %1;" : "=r"(u) : "f"(a)); return __uint_as_float(u);
}
__device__ __forceinline__ void mma8(float* d, const uint32_t* a, const uint32_t* b){
    asm volatile("mma.sync.aligned.m16n8k8.row.col.f32.tf32.tf32.f32 "
        "{%0,%1,%2,%3}, {%4,%5,%6,%7}, {%8,%9}, {%0,%1,%2,%3};"
        : "+f"(d[0]), "+f"(d[1]), "+f"(d[2]), "+f"(d[3])
        : "r"(a[0]), "r"(a[1]), "r"(a[2]), "r"(a[3]), "r"(b[0]), "r"(b[1]));
}
__device__ __forceinline__ uint32_t smem_u32(const void* p){
    uint32_t a; asm("{ .reg .u64 t; cvta.to.shared.u64 t, %1; cvt.u32.u64 %0, t; }" : "=r"(a) : "l"(p));
    return a;
}
__device__ __forceinline__ void cpa16(uint32_t saddr, const float* g){
    asm volatile("cp.async.ca.shared.global [%0], [%1], 16;" :: "r"(saddr), "l"(g));
}
#define CP_COMMIT() asm volatile("cp.async.commit_group;" ::: "memory")
#define CP_WAIT1()  asm volatile("cp.async.wait_group 1;" ::: "memory")
#define CP_WAIT0()  asm volatile("cp.async.wait_group 0;" ::: "memory")

// ---------------- tile geometry (256 thr, 128x128, BK=32) ----------------
#define PA0 36
#define PA1 136
#define PB  136
#define A_FL (128*PA0)     // 4608 floats
#define B_FL (32*PB)       // 4352 floats
#define STAGE_FL (A_FL + B_FL)          // 8960
#define SMEM_DB (2*STAGE_FL*4)          // 71680 bytes

// k_kv smem layout (floats)
#define KV_AS   0            // 2 x 32*PA1 = 2*4352
#define KV_BS   (2*4352)     // 2 x 32*PB
#define KV_PK   (4*4352)     // 2 x 4096
#define KV_PV   (4*4352 + 2*4096)
#define KV_FL   (4*4352 + 4*4096)       // 33792 floats
#define SMEM_KV (KV_FL*4)               // 135168 bytes

// fragment math on one staged chunk (AMODE 0: A [m][k])
__device__ __forceinline__ void math_chunk0(const float* As, const float* Bs, float acc[2][8][4],
                                            int wm, int wn, int g, int c4){
    #pragma unroll
    for (int ks = 0; ks < 4; ks++){
        const int kb = ks*8;
        uint32_t a[2][4], bf[8][2];
        #pragma unroll
        for (int mf = 0; mf < 2; mf++){
            int row = wm*32 + mf*16 + g;
            a[mf][0] = __float_as_uint(As[(row  )*PA0 + kb + c4    ]);
            a[mf][1] = __float_as_uint(As[(row+8)*PA0 + kb + c4    ]);
            a[mf][2] = __float_as_uint(As[(row  )*PA0 + kb + c4 + 4]);
            a[mf][3] = __float_as_uint(As[(row+8)*PA0 + kb + c4 + 4]);
        }
        #pragma unroll
        for (int nf = 0; nf < 8; nf++){
            int ncol = wn*64 + nf*8 + g;
            bf[nf][0] = __float_as_uint(Bs[(kb+c4  )*PB + ncol]);
            bf[nf][1] = __float_as_uint(Bs[(kb+c4+4)*PB + ncol]);
        }
        #pragma unroll
        for (int mf = 0; mf < 2; mf++)
            #pragma unroll
            for (int nf = 0; nf < 8; nf++)
                mma8(acc[mf][nf], a[mf], bf[nf]);
    }
}

// MN-major fragment math (A in [k][m] layout, stride PA1)
__device__ __forceinline__ void math_chunk1(const float* As, const float* Bs, float acc[2][8][4],
                                            int wm, int wn, int g, int c4){
    #pragma unroll
    for (int kss = 0; kss < 4; kss++){
        const int kb = kss*8;
        uint32_t a[2][4], bf[8][2];
        #pragma unroll
        for (int mf = 0; mf < 2; mf++){
            int row = wm*32 + mf*16 + g;
            a[mf][0] = __float_as_uint(As[(kb+c4  )*PA1 + row    ]);
            a[mf][1] = __float_as_uint(As[(kb+c4  )*PA1 + row + 8]);
            a[mf][2] = __float_as_uint(As[(kb+c4+4)*PA1 + row    ]);
            a[mf][3] = __float_as_uint(As[(kb+c4+4)*PA1 + row + 8]);
        }
        #pragma unroll
        for (int nf = 0; nf < 8; nf++){
            int ncol = wn*64 + nf*8 + g;
            bf[nf][0] = __float_as_uint(Bs[(kb+c4  )*PB + ncol]);
            bf[nf][1] = __float_as_uint(Bs[(kb+c4+4)*PB + ncol]);
        }
        #pragma unroll
        for (int mf = 0; mf < 2; mf++)
            #pragma unroll
            for (int nf = 0; nf < 8; nf++)
                mma8(acc[mf][nf], a[mf], bf[nf]);
    }
}

// async stage of one chunk (raw bytes, no cvt) into stage buffer s
__device__ __forceinline__ void stage_async(uint32_t su, int s, const float* A, int lda,
                                            const float* B, int ldb, int ch, int tid){
    uint32_t base = su + (uint32_t)(s*STAGE_FL*4);
    #pragma unroll
    for (int i = 0; i < 4; i++){
        int idx = tid + i*256;           // A: 1024 float4 (128m x 8kq)
        int m = idx >> 3, kq = idx & 7;
        cpa16(base + (uint32_t)(m*PA0 + kq*4)*4, A + (size_t)m*lda + ch*32 + kq*4);
    }
    uint32_t bbase = base + A_FL*4;
    #pragma unroll
    for (int i = 0; i < 4; i++){
        int idx = tid + i*256;           // B: 1024 float4 (32k x 32nq)
        int kr = idx >> 5, nq = idx & 31;
        cpa16(bbase + (uint32_t)(kr*PB + nq*4)*4, B + (size_t)(ch*32 + kr)*ldb + nq*4);
    }
}

// in-place RNA tf32 convert of the bytes THIS thread staged (own-data, pre-sync ok)
__device__ __forceinline__ void convert_stage(float* sm, int s, int tid){
    float* base = sm + s*STAGE_FL;
    #pragma unroll
    for (int i = 0; i < 4; i++){
        int idx = tid + i*256;
        int m = idx >> 3, kq = idx & 7;
        float4* p = reinterpret_cast<float4*>(base + m*PA0 + kq*4);
        float4 v = *p;
        v.x=t32(v.x); v.y=t32(v.y); v.z=t32(v.z); v.w=t32(v.w);
        *p = v;
    }
    float* bb = base + A_FL;
    #pragma unroll
    for (int i = 0; i < 4; i++){
        int idx = tid + i*256;
        int kr = idx >> 5, nq = idx & 31;
        float4* p = reinterpret_cast<float4*>(bb + kr*PB + nq*4);
        float4 v = *p;
        v.x=t32(v.x); v.y=t32(v.y); v.z=t32(v.z); v.w=t32(v.w);
        *p = v;
    }
}

// double-buffered async GEMM mainloop. CVT=1: raw fp32 inputs (convert in place).
template<int CVT>
__device__ __forceinline__ void gemm_async(const float* A, int lda, const float* B, int ldb,
                                           int kchunks, float acc[2][8][4], float* sm, uint32_t su){
    const int tid = threadIdx.x, lane = tid & 31, wid = tid >> 5;
    const int wm = wid & 3, wn = wid >> 2, g = lane >> 2, c4 = lane & 3;
    #pragma unroll
    for (int mf = 0; mf < 2; mf++)
        #pragma unroll
        for (int nf = 0; nf < 8; nf++)
            #pragma unroll
            for (int j = 0; j < 4; j++) acc[mf][nf][j] = 0.f;

    stage_async(su, 0, A, lda, B, ldb, 0, tid);
    CP_COMMIT();
    for (int ch = 0; ch < kchunks; ch++){
        int cur = ch & 1;
        CP_WAIT0();
        if (CVT) convert_stage(sm, cur, tid);
        __syncthreads();
        if (ch + 1 < kchunks){
            stage_async(su, cur ^ 1, A, lda, B, ldb, ch + 1, tid);
            CP_COMMIT();
        }
        math_chunk0(sm + cur*STAGE_FL, sm + cur*STAGE_FL + A_FL, acc, wm, wn, g, c4);
        __syncthreads();
    }
}

// ================= k_phi: phi = sigmoid(X @ W + b) + fused reductions =================
__global__ __launch_bounds__(256, 2) void k_phi(const float* __restrict__ X,
                                                const float* __restrict__ W,
                                                const float* __restrict__ bias, int which){
    extern __shared__ float sm[];
    uint32_t su = smem_u32(sm);
    float* out = which ? g_phik : g_phiq;
    const int m0 = blockIdx.y * 128, e0 = blockIdx.x * 128;
    float acc[2][8][4];
    gemm_async<1>(X + (size_t)m0*DD, DD, W + e0, DD, 8, acc, sm, su);

    const int tid = threadIdx.x, lane = tid & 31, wid = tid >> 5;
    const int wm = wid & 3, wn = wid >> 2, g = lane >> 2, c4 = lane & 3;

    float rpart[2][2] = {{0.f,0.f},{0.f,0.f}};
    float cpart[8][2];
    #pragma unroll
    for (int nf = 0; nf < 8; nf++){ cpart[nf][0]=0.f; cpart[nf][1]=0.f; }

    #pragma unroll
    for (int mf = 0; mf < 2; mf++){
        int row = m0 + wm*32 + mf*16 + g;
        #pragma unroll
        for (int nf = 0; nf < 8; nf++){
            int lcol = wn*64 + nf*8 + c4*2;
            float b0 = bias[e0 + lcol], b1 = bias[e0 + lcol + 1];
            float s00 = sigf(acc[mf][nf][0] + b0), s01 = sigf(acc[mf][nf][1] + b1);
            float s10 = sigf(acc[mf][nf][2] + b0), s11 = sigf(acc[mf][nf][3] + b1);
            float2 r0 = { t32(s00), t32(s01) };
            float2 r1 = { t32(s10), t32(s11) };
            *reinterpret_cast<float2*>(out + (size_t)row*DD + e0 + lcol)     = r0;
            *reinterpret_cast<float2*>(out + (size_t)(row+8)*DD + e0 + lcol) = r1;
            rpart[mf][0] += s00 + s01;
            rpart[mf][1] += s10 + s11;
            cpart[nf][0] += s00 + s10;
            cpart[nf][1] += s01 + s11;
        }
    }
    __syncthreads();   // staging buffers free; reuse sm for reductions

    if (!which){
        #pragma unroll
        for (int mf = 0; mf < 2; mf++)
            #pragma unroll
            for (int h = 0; h < 2; h++){
                rpart[mf][h] += __shfl_xor_sync(0xffffffffu, rpart[mf][h], 1);
                rpart[mf][h] += __shfl_xor_sync(0xffffffffu, rpart[mf][h], 2);
            }
        if (c4 == 0){
            #pragma unroll
            for (int mf = 0; mf < 2; mf++){
                int r = wm*32 + mf*16 + g;
                sm[wn*128 + r]     = rpart[mf][0];
                sm[wn*128 + r + 8] = rpart[mf][1];
            }
        }
        __syncthreads();
        if (tid < 128)
            g_rowpart[(size_t)blockIdx.x*BN_TOT + m0 + tid] = sm[tid] + sm[128 + tid];
    } else {
        #pragma unroll
        for (int nf = 0; nf < 8; nf++)
            #pragma unroll
            for (int h = 0; h < 2; h++){
                cpart[nf][h] += __shfl_xor_sync(0xffffffffu, cpart[nf][h], 4);
                cpart[nf][h] += __shfl_xor_sync(0xffffffffu, cpart[nf][h], 8);
                cpart[nf][h] += __shfl_xor_sync(0xffffffffu, cpart[nf][h], 16);
            }
        if (g == 0){
            #pragma unroll
            for (int nf = 0; nf < 8; nf++){
                int lcol = wn*64 + nf*8 + c4*2;
                sm[wm*128 + lcol]     = cpart[nf][0];
                sm[wm*128 + lcol + 1] = cpart[nf][1];
            }
        }
        __syncthreads();
        if (tid < 128){
            float s = ((sm[tid] + sm[128+tid]) + (sm[256+tid] + sm[384+tid]));
            int b = m0 >> 12, mt = (m0 >> 7) & 31;
            g_colpart2[((b*32 + mt) << 8) + e0 + tid] = s;
        }
    }
}

// ================= k_colsum =================
__global__ __launch_bounds__(256) void k_colsum(){
    int idx = blockIdx.x*256 + threadIdx.x;       // b*DD + d
    int b = idx >> 8, d = idx & 255;
    float s = 0.f;
    #pragma unroll
    for (int mt = 0; mt < 32; mt++) s += g_colpart2[((b*32+mt)<<8) + d];
    g_colsum[idx] = s;
}

// ================= k_kv: fully-async pipelined KV' partials + Z =================
// grid (2 e-tiles, 2 d-tiles, BB*2 b*ks); split-K x2, 64 chunks, 1 sync/chunk.
__global__ __launch_bounds__(256, 1) void k_kv(const float* __restrict__ V){
    extern __shared__ float sm[];
    uint32_t su = smem_u32(sm);
    __shared__ float cinv[128];
    __shared__ float zsm[8*128];
    const int tid = threadIdx.x, lane = tid & 31, wid = tid >> 5;
    const int wm = wid & 3, wn = wid >> 2, g = lane >> 2, c4 = lane & 3;
    const int e0 = blockIdx.x * 128, d0 = blockIdx.y * 128;
    const int b = blockIdx.z >> 1, ks = blockIdx.z & 1;
    const float* A  = g_phik + (size_t)(b*NN + ks*2048)*DD + d0;
    const float* PK = g_phik + (size_t)(b*NN + ks*2048)*DD + e0;
    const float* PV = V      + (size_t)(b*NN + ks*2048)*DD + e0;

    if (tid < 128) cinv[tid] = 1.0f/(g_colsum[b*DD + e0 + tid] + EPSF);

    float acc[2][8][4];
    #pragma unroll
    for (int mf = 0; mf < 2; mf++)
        #pragma unroll
        for (int nf = 0; nf < 8; nf++)
            #pragma unroll
            for (int j = 0; j < 4; j++) acc[mf][nf][j] = 0.f;

    const int nq = tid & 31;             // column quad, fixed per thread
    const int krb = tid >> 5;            // base row, rows krb+8i
    float z[4] = {0.f, 0.f, 0.f, 0.f};

    // stage chunk 0: A (As buf0), PK, PV raw
    {
        #pragma unroll
        for (int i = 0; i < 4; i++){
            int idx = tid + i*256;
            int kr = idx >> 5, mq = idx & 31;
            cpa16(su + (uint32_t)(KV_AS + kr*PA1 + mq*4)*4, A + (size_t)kr*DD + mq*4);
        }
        #pragma unroll
        for (int i = 0; i < 4; i++){
            int kr = krb + i*8;
            cpa16(su + (uint32_t)(KV_PK + kr*128 + nq*4)*4, PK + (size_t)kr*DD + nq*4);
            cpa16(su + (uint32_t)(KV_PV + kr*128 + nq*4)*4, PV + (size_t)kr*DD + nq*4);
        }
        CP_COMMIT();
    }
    __syncthreads();    // cinv visible (also orders nothing else)

    float cx = cinv[nq*4], cy = cinv[nq*4+1], cz = cinv[nq*4+2], cw = cinv[nq*4+3];

    for (int ch = 0; ch < 64; ch++){
        const int cur = ch & 1;
        CP_WAIT0();
        // exp phase: SMEM->SMEM, each thread touches only bytes it staged
        float* pk = sm + KV_PK + cur*4096;
        float* pv = sm + KV_PV + cur*4096;
        float* bs = sm + KV_BS + cur*4352;
        #pragma unroll
        for (int i = 0; i < 4; i++){
            int kr = krb + i*8;
            float4 a = *reinterpret_cast<float4*>(pk + kr*128 + nq*4);
            float4 v = *reinterpret_cast<float4*>(pv + kr*128 + nq*4);
            float ex = __expf(a.x*v.x*cx);
            float ey = __expf(a.y*v.y*cy);
            float ez = __expf(a.z*v.z*cz);
            float ew = __expf(a.w*v.w*cw);
            z[0] += ex; z[1] += ey; z[2] += ez; z[3] += ew;
            float4 r = { t32(ex), t32(ey), t32(ez), t32(ew) };
            *reinterpret_cast<float4*>(bs + kr*PB + nq*4) = r;
        }
        __syncthreads();  // Bs[cur] visible; all threads past math(ch-1) (bufs cur^1 free)
        if (ch + 1 < 64){
            const int nxt = cur ^ 1;
            const size_t roff = (size_t)(ch + 1)*32;
            #pragma unroll
            for (int i = 0; i < 4; i++){
                int idx = tid + i*256;
                int kr = idx >> 5, mq = idx & 31;
                cpa16(su + (uint32_t)(KV_AS + nxt*4352 + kr*PA1 + mq*4)*4,
                      A + (roff + kr)*DD + mq*4);
            }
            #pragma unroll
            for (int i = 0; i < 4; i++){
                int kr = krb + i*8;
                cpa16(su + (uint32_t)(KV_PK + nxt*4096 + kr*128 + nq*4)*4,
                      PK + (roff + kr)*DD + nq*4);
                cpa16(su + (uint32_t)(KV_PV + nxt*4096 + kr*128 + nq*4)*4,
                      PV + (roff + kr)*DD + nq*4);
            }
            CP_COMMIT();
        }
        math_chunk1(sm + KV_AS + cur*4352, sm + KV_BS + cur*4352, acc, wm, wn, g, c4);
        // no trailing sync: next iter writes only cur^1 buffers (own-thread PK/PV reads)
    }

    // Z partials (deterministic fixed-order combine)
    __syncthreads();
    #pragma unroll
    for (int j = 0; j < 4; j++) zsm[wid*128 + nq*4 + j] = z[j];
    __syncthreads();
    if (blockIdx.y == 0 && tid < 128){
        float Z = 0.f;
        #pragma unroll
        for (int w = 0; w < 8; w++) Z += zsm[w*128 + tid];
        g_zpart[(b*2 + ks)*DD + e0 + tid] = Z;
    }

    float* part = g_kvpart + (size_t)(ks*BB + b)*DD*DD;
    #pragma unroll
    for (int mf = 0; mf < 2; mf++){
        int row = d0 + wm*32 + mf*16 + g;
        #pragma unroll
        for (int nf = 0; nf < 8; nf++){
            int col = e0 + wn*64 + nf*8 + c4*2;
            float2 r0 = { acc[mf][nf][0], acc[mf][nf][1] };
            float2 r1 = { acc[mf][nf][2], acc[mf][nf][3] };
            *reinterpret_cast<float2*>(part + (size_t)row*DD + col)     = r0;
            *reinterpret_cast<float2*>(part + (size_t)(row+8)*DD + col) = r1;
        }
    }
}

// ================= k_kvscale: kv = (Σ ks parts) / Z[e], tf32-rounded =================
__global__ __launch_bounds__(256) void k_kvscale(){
    int idx = blockIdx.x*256 + threadIdx.x;       // b*DD*DD + d*DD + e
    const int S = BB*DD*DD;
    int e = idx & 255, b = idx >> 16;
    int zb = b*2*DD + e;
    float Z = g_zpart[zb] + g_zpart[zb + DD];
    float v = g_kvpart[idx] + g_kvpart[idx + S];
    g_kv[idx] = t32(v / Z);
}

// ================= k_out: R = gate(rowsum) * (phi_q @ KV[b]) =================
__global__ __launch_bounds__(256, 2) void k_out(float* __restrict__ out){
    extern __shared__ float sm[];
    uint32_t su = smem_u32(sm);
    const int m0 = blockIdx.y * 128, e0 = blockIdx.x * 128;
    const int b = m0 >> 12;
    float acc[2][8][4];
    gemm_async<0>(g_phiq + (size_t)m0*DD, DD, g_kv + (size_t)b*DD*DD + e0, DD, 8, acc, sm, su);

    const int tid = threadIdx.x, lane = tid & 31, wid = tid >> 5;
    const int wm = wid & 3, wn = wid >> 2, g = lane >> 2, c4 = lane & 3;
    #pragma unroll
    for (int mf = 0; mf < 2; mf++){
        int row = m0 + wm*32 + mf*16 + g;
        float rs0 = g_rowpart[row]   + g_rowpart[BN_TOT + row];
        float rs1 = g_rowpart[row+8] + g_rowpart[BN_TOT + row + 8];
        float sc0 = sigf(rs0) / (rs0 + EPSF);
        float sc1 = sigf(rs1) / (rs1 + EPSF);
        #pragma unroll
        for (int nf = 0; nf < 8; nf++){
            int col = e0 + wn*64 + nf*8 + c4*2;
            float2 r0 = { acc[mf][nf][0]*sc0, acc[mf][nf][1]*sc0 };
            float2 r1 = { acc[mf][nf][2]*sc1, acc[mf][nf][3]*sc1 };
            *reinterpret_cast<float2*>(out + (size_t)row*DD + col)     = r0;
            *reinterpret_cast<float2*>(out + (size_t)(row+8)*DD + col) = r1;
        }
    }
}

// ================= launch =================
extern "C" void kernel_launch(void* const* d_in, const int* in_sizes, int n_in,
                              void* d_out, int out_size){
    const float* Q  = (const float*)d_in[0];
    const float* K  = (const float*)d_in[1];
    const float* V  = (const float*)d_in[2];
    const float* Wq = (const float*)d_in[3];
    const float* bq = (const float*)d_in[4];
    const float* Wk = (const float*)d_in[5];
    const float* bk = (const float*)d_in[6];
    float* out = (float*)d_out;
    (void)in_sizes; (void)n_in; (void)out_size;

    cudaFuncSetAttribute(k_phi, cudaFuncAttributeMaxDynamicSharedMemorySize, SMEM_DB);
    cudaFuncSetAttribute(k_out, cudaFuncAttributeMaxDynamicSharedMemorySize, SMEM_DB);
    cudaFuncSetAttribute(k_kv,  cudaFuncAttributeMaxDynamicSharedMemorySize, SMEM_KV);

    k_phi<<<dim3(2,512), 256, SMEM_DB>>>(Q, Wq, bq, 0);   // phi_q + rowsum partials
    k_phi<<<dim3(2,512), 256, SMEM_DB>>>(K, Wk, bk, 1);   // phi_k + colsum partials
    k_colsum<<<16, 256>>>();
    k_kv<<<dim3(2,2,BB*2), 256, SMEM_KV>>>(V);            // KV' partials + Z (pipelined)
    k_kvscale<<<BB*DD*DD/256, 256>>>();
    k_out<<<dim3(2,512), 256, SMEM_DB>>>(out);            // final R
}

// round 11
// speedup vs baseline: 1.4444x; 1.0926x over previous
#include <cuda_runtime.h>
#include <cstdint>

#define BB 16
#define NN 4096
#define DD 256
#define BN_TOT (BB*NN)          // 65536
#define EPSF 1e-6f

// ---------------- scratch ----------------
__device__ unsigned short g_phiq[BN_TOT*DD];   // [bn][d] bf16, 32MB
__device__ unsigned short g_phik[BN_TOT*DD];   // [bn][d] bf16, 32MB
__device__ float g_rowpart[2*BN_TOT];
__device__ float g_colpart2[BB*32*DD];
__device__ float g_colsum[BB*DD];
__device__ float g_zpart[BB*4*DD];             // Z partials per ks (4)
__device__ float g_kvpart[4*BB*DD*DD];         // split-K KV partials [d][e]
__device__ unsigned short g_kvT[BB*DD*DD];     // bf16, TRANSPOSED [b][e][d]

__device__ __forceinline__ float sigf(float x){ return 1.0f/(1.0f + __expf(-x)); }
__device__ __forceinline__ float t32(float a){
    uint32_t u; asm("cvt.rna.tf32.f32 %0, %1;" : "=r"(u) : "f"(a)); return __uint_as_float(u);
}
__device__ __forceinline__ uint32_t pack_bf2(float lo, float hi){
    uint32_t r; asm("cvt.rn.bf16x2.f32 %0, %1, %2;" : "=r"(r) : "f"(hi), "f"(lo)); return r;
}
__device__ __forceinline__ void mma8(float* d, const uint32_t* a, const uint32_t* b){
    asm volatile("mma.sync.aligned.m16n8k8.row.col.f32.tf32.tf32.f32 "
        "{%0,%1,%2,%3}, {%4,%5,%6,%7}, {%8,%9}, {%0,%1,%2,%3};"
        : "+f"(d[0]), "+f"(d[1]), "+f"(d[2]), "+f"(d[3])
        : "r"(a[0]), "r"(a[1]), "r"(a[2]), "r"(a[3]), "r"(b[0]), "r"(b[1]));
}
__device__ __forceinline__ void mma16(float* d, const uint32_t* a, const uint32_t* b){
    asm volatile("mma.sync.aligned.m16n8k16.row.col.f32.bf16.bf16.f32 "
        "{%0,%1,%2,%3}, {%4,%5,%6,%7}, {%8,%9}, {%0,%1,%2,%3};"
        : "+f"(d[0]), "+f"(d[1]), "+f"(d[2]), "+f"(d[3])
        : "r"(a[0]), "r"(a[1]), "r"(a[2]), "r"(a[3]), "r"(b[0]), "r"(b[1]));
}
__device__ __forceinline__ uint32_t smem_u32(const void* p){
    uint32_t a; asm("{ .reg .u64 t; cvta.to.shared.u64 t, %1; cvt.u32.u64 %0, t; }" : "=r"(a) : "l"(p));
    return a;
}
__device__ __forceinline__ void cpa16(uint32_t saddr, const void* g){
    asm volatile("cp.async.ca.shared.global [%0], [%1], 16;" :: "r"(saddr), "l"(g));
}
#define CP_COMMIT() asm volatile("cp.async.commit_group;" ::: "memory")
#define CP_WAIT0()  asm volatile("cp.async.wait_group 0;" ::: "memory")

// ================= tf32 core (k_phi): 256 thr, 128x128, BK=32 =================
#define PA0 36
#define PB  136
#define A_FL (128*PA0)
#define B_FL (32*PB)
#define STAGE_FL (A_FL + B_FL)          // 8960 floats
#define SMEM_DB (2*STAGE_FL*4)          // 71680

__device__ __forceinline__ void math_chunk0(const float* As, const float* Bs, float acc[2][8][4],
                                            int wm, int wn, int g, int c4){
    #pragma unroll
    for (int ks = 0; ks < 4; ks++){
        const int kb = ks*8;
        uint32_t a[2][4], bf[8][2];
        #pragma unroll
        for (int mf = 0; mf < 2; mf++){
            int row = wm*32 + mf*16 + g;
            a[mf][0] = __float_as_uint(As[(row  )*PA0 + kb + c4    ]);
            a[mf][1] = __float_as_uint(As[(row+8)*PA0 + kb + c4    ]);
            a[mf][2] = __float_as_uint(As[(row  )*PA0 + kb + c4 + 4]);
            a[mf][3] = __float_as_uint(As[(row+8)*PA0 + kb + c4 + 4]);
        }
        #pragma unroll
        for (int nf = 0; nf < 8; nf++){
            int ncol = wn*64 + nf*8 + g;
            bf[nf][0] = __float_as_uint(Bs[(kb+c4  )*PB + ncol]);
            bf[nf][1] = __float_as_uint(Bs[(kb+c4+4)*PB + ncol]);
        }
        #pragma unroll
        for (int mf = 0; mf < 2; mf++)
            #pragma unroll
            for (int nf = 0; nf < 8; nf++)
                mma8(acc[mf][nf], a[mf], bf[nf]);
    }
}

__device__ __forceinline__ void stage_async(uint32_t su, int s, const float* A, int lda,
                                            const float* B, int ldb, int ch, int tid){
    uint32_t base = su + (uint32_t)(s*STAGE_FL*4);
    #pragma unroll
    for (int i = 0; i < 4; i++){
        int idx = tid + i*256;
        int m = idx >> 3, kq = idx & 7;
        cpa16(base + (uint32_t)(m*PA0 + kq*4)*4, A + (size_t)m*lda + ch*32 + kq*4);
    }
    uint32_t bbase = base + A_FL*4;
    #pragma unroll
    for (int i = 0; i < 4; i++){
        int idx = tid + i*256;
        int kr = idx >> 5, nq = idx & 31;
        cpa16(bbase + (uint32_t)(kr*PB + nq*4)*4, B + (size_t)(ch*32 + kr)*ldb + nq*4);
    }
    CP_COMMIT();
}

__device__ __forceinline__ void convert_stage(float* sm, int s, int tid){
    float* base = sm + s*STAGE_FL;
    #pragma unroll
    for (int i = 0; i < 4; i++){
        int idx = tid + i*256;
        int m = idx >> 3, kq = idx & 7;
        float4* p = reinterpret_cast<float4*>(base + m*PA0 + kq*4);
        float4 v = *p;
        v.x=t32(v.x); v.y=t32(v.y); v.z=t32(v.z); v.w=t32(v.w);
        *p = v;
    }
    float* bb = base + A_FL;
    #pragma unroll
    for (int i = 0; i < 4; i++){
        int idx = tid + i*256;
        int kr = idx >> 5, nq = idx & 31;
        float4* p = reinterpret_cast<float4*>(bb + kr*PB + nq*4);
        float4 v = *p;
        v.x=t32(v.x); v.y=t32(v.y); v.z=t32(v.z); v.w=t32(v.w);
        *p = v;
    }
}

__device__ __forceinline__ void gemm_async(const float* A, int lda, const float* B, int ldb,
                                           int kchunks, float acc[2][8][4], float* sm, uint32_t su){
    const int tid = threadIdx.x, lane = tid & 31, wid = tid >> 5;
    const int wm = wid & 3, wn = wid >> 2, g = lane >> 2, c4 = lane & 3;
    #pragma unroll
    for (int mf = 0; mf < 2; mf++)
        #pragma unroll
        for (int nf = 0; nf < 8; nf++)
            #pragma unroll
            for (int j = 0; j < 4; j++) acc[mf][nf][j] = 0.f;

    stage_async(su, 0, A, lda, B, ldb, 0, tid);
    for (int ch = 0; ch < kchunks; ch++){
        int cur = ch & 1;
        CP_WAIT0();
        convert_stage(sm, cur, tid);
        __syncthreads();
        if (ch + 1 < kchunks)
            stage_async(su, cur ^ 1, A, lda, B, ldb, ch + 1, tid);
        math_chunk0(sm + cur*STAGE_FL, sm + cur*STAGE_FL + A_FL, acc, wm, wn, g, c4);
    }
    __syncthreads();
}

// ================= k_phi: phi = sigmoid(X @ W + b) -> bf16, fused reductions ======
__global__ __launch_bounds__(256, 2) void k_phi(const float* __restrict__ X,
                                                const float* __restrict__ W,
                                                const float* __restrict__ bias, int which){
    extern __shared__ float sm[];
    uint32_t su = smem_u32(sm);
    unsigned short* out = which ? g_phik : g_phiq;
    const int m0 = blockIdx.y * 128, e0 = blockIdx.x * 128;
    float acc[2][8][4];
    gemm_async(X + (size_t)m0*DD, DD, W + e0, DD, 8, acc, sm, su);

    const int tid = threadIdx.x, lane = tid & 31, wid = tid >> 5;
    const int wm = wid & 3, wn = wid >> 2, g = lane >> 2, c4 = lane & 3;

    float rpart[2][2] = {{0.f,0.f},{0.f,0.f}};
    float cpart[8][2];
    #pragma unroll
    for (int nf = 0; nf < 8; nf++){ cpart[nf][0]=0.f; cpart[nf][1]=0.f; }

    #pragma unroll
    for (int mf = 0; mf < 2; mf++){
        int row = m0 + wm*32 + mf*16 + g;
        #pragma unroll
        for (int nf = 0; nf < 8; nf++){
            int lcol = wn*64 + nf*8 + c4*2;
            float b0 = bias[e0 + lcol], b1 = bias[e0 + lcol + 1];
            float s00 = sigf(acc[mf][nf][0] + b0), s01 = sigf(acc[mf][nf][1] + b1);
            float s10 = sigf(acc[mf][nf][2] + b0), s11 = sigf(acc[mf][nf][3] + b1);
            *reinterpret_cast<uint32_t*>(out + (size_t)row*DD + e0 + lcol)     = pack_bf2(s00, s01);
            *reinterpret_cast<uint32_t*>(out + (size_t)(row+8)*DD + e0 + lcol) = pack_bf2(s10, s11);
            rpart[mf][0] += s00 + s01;
            rpart[mf][1] += s10 + s11;
            cpart[nf][0] += s00 + s10;
            cpart[nf][1] += s01 + s11;
        }
    }
    __syncthreads();

    if (!which){
        #pragma unroll
        for (int mf = 0; mf < 2; mf++)
            #pragma unroll
            for (int h = 0; h < 2; h++){
                rpart[mf][h] += __shfl_xor_sync(0xffffffffu, rpart[mf][h], 1);
                rpart[mf][h] += __shfl_xor_sync(0xffffffffu, rpart[mf][h], 2);
            }
        if (c4 == 0){
            #pragma unroll
            for (int mf = 0; mf < 2; mf++){
                int r = wm*32 + mf*16 + g;
                sm[wn*128 + r]     = rpart[mf][0];
                sm[wn*128 + r + 8] = rpart[mf][1];
            }
        }
        __syncthreads();
        if (tid < 128)
            g_rowpart[(size_t)blockIdx.x*BN_TOT + m0 + tid] = sm[tid] + sm[128 + tid];
    } else {
        #pragma unroll
        for (int nf = 0; nf < 8; nf++)
            #pragma unroll
            for (int h = 0; h < 2; h++){
                cpart[nf][h] += __shfl_xor_sync(0xffffffffu, cpart[nf][h], 4);
                cpart[nf][h] += __shfl_xor_sync(0xffffffffu, cpart[nf][h], 8);
                cpart[nf][h] += __shfl_xor_sync(0xffffffffu, cpart[nf][h], 16);
            }
        if (g == 0){
            #pragma unroll
            for (int nf = 0; nf < 8; nf++){
                int lcol = wn*64 + nf*8 + c4*2;
                sm[wm*128 + lcol]     = cpart[nf][0];
                sm[wm*128 + lcol + 1] = cpart[nf][1];
            }
        }
        __syncthreads();
        if (tid < 128){
            float s = ((sm[tid] + sm[128+tid]) + (sm[256+tid] + sm[384+tid]));
            int b = m0 >> 12, mt = (m0 >> 7) & 31;
            g_colpart2[((b*32 + mt) << 8) + e0 + tid] = s;
        }
    }
}

// ================= k_colsum =================
__global__ __launch_bounds__(256) void k_colsum(){
    int idx = blockIdx.x*256 + threadIdx.x;
    int b = idx >> 8, d = idx & 255;
    float s = 0.f;
    #pragma unroll
    for (int mt = 0; mt < 32; mt++) s += g_colpart2[((b*32+mt)<<8) + d];
    g_colsum[idx] = s;
}

// ================= k_kv: bf16-staged, 2 CTA/SM, split-K x4, tf32 MMA ============
#define AS_S 8704               // 32*136 bf16 bytes
#define BS_S 17408              // 32*136 fp32 bytes
#define PK_S 8192               // 32*128 bf16 bytes
#define PV_S 16384              // 32*128 fp32 bytes
#define KVB_AS 0
#define KVB_BS (2*AS_S)         // 17408
#define KVB_PK (KVB_BS + 2*BS_S)// 52224
#define KVB_PV (KVB_PK + 2*PK_S)// 68608
#define SMEM_KV (KVB_PV + 2*PV_S)// 101376
#define PA1H 136

__device__ __forceinline__ void kv_stage(uint32_t su, int buf,
                                         const unsigned short* A, const unsigned short* PK,
                                         const float* PV, size_t roff, int tid, int cq, int rb){
    #pragma unroll
    for (int i = 0; i < 2; i++){
        int idx = tid + i*256;
        int kr = idx >> 4, dq = idx & 15;
        cpa16(su + KVB_AS + (uint32_t)(buf*AS_S + kr*272 + dq*16), A + (roff+kr)*DD + dq*8);
    }
    #pragma unroll
    for (int r = 0; r < 2; r++){
        int kr = rb + r*16;
        cpa16(su + KVB_PK + (uint32_t)(buf*PK_S + kr*256 + cq*16),      PK + (roff+kr)*DD + cq*8);
        cpa16(su + KVB_PV + (uint32_t)(buf*PV_S + kr*512 + cq*32),      PV + (roff+kr)*DD + cq*8);
        cpa16(su + KVB_PV + (uint32_t)(buf*PV_S + kr*512 + cq*32 + 16), PV + (roff+kr)*DD + cq*8 + 4);
    }
    CP_COMMIT();
}

__global__ __launch_bounds__(256, 2) void k_kv(const float* __restrict__ V){
    extern __shared__ char smc[];
    uint32_t su = smem_u32(smc);
    __shared__ float cinvs[128];
    __shared__ float zsm[16*128];
    const int tid = threadIdx.x, lane = tid & 31, wid = tid >> 5;
    const int wm = wid & 3, wn = wid >> 2, g = lane >> 2, c4 = lane & 3;
    const int e0 = blockIdx.x * 128, d0 = blockIdx.y * 128;
    const int b = blockIdx.z >> 2, ks = blockIdx.z & 3;
    const unsigned short* A  = g_phik + (size_t)(b*NN + ks*1024)*DD + d0;
    const unsigned short* PK = g_phik + (size_t)(b*NN + ks*1024)*DD + e0;
    const float* PV = V + (size_t)(b*NN + ks*1024)*DD + e0;

    if (tid < 128) cinvs[tid] = 1.0f/(g_colsum[b*DD + e0 + tid] + EPSF);

    float acc[2][8][4];
    #pragma unroll
    for (int mf = 0; mf < 2; mf++)
        #pragma unroll
        for (int nf = 0; nf < 8; nf++)
            #pragma unroll
            for (int j = 0; j < 4; j++) acc[mf][nf][j] = 0.f;

    const int cq = tid & 15;     // 8-col group
    const int rb = tid >> 4;     // rows rb, rb+16
    float z[8] = {0.f,0.f,0.f,0.f,0.f,0.f,0.f,0.f};

    kv_stage(su, 0, A, PK, PV, 0, tid, cq, rb);
    __syncthreads();
    float ci[8];
    #pragma unroll
    for (int j = 0; j < 8; j++) ci[j] = cinvs[cq*8 + j];

    for (int ch = 0; ch < 32; ch++){
        const int cur = ch & 1;
        CP_WAIT0();
        // exp phase: own-staged bytes only
        {
            char* pkb = smc + KVB_PK + cur*PK_S;
            char* pvb = smc + KVB_PV + cur*PV_S;
            char* bsb = smc + KVB_BS + cur*BS_S;
            #pragma unroll
            for (int r = 0; r < 2; r++){
                int kr = rb + r*16;
                uint4  pw = *reinterpret_cast<uint4*>(pkb + kr*256 + cq*16);
                float4 v0 = *reinterpret_cast<float4*>(pvb + kr*512 + cq*32);
                float4 v1 = *reinterpret_cast<float4*>(pvb + kr*512 + cq*32 + 16);
                float p0 = __uint_as_float(pw.x << 16), p1 = __uint_as_float(pw.x & 0xFFFF0000u);
                float p2 = __uint_as_float(pw.y << 16), p3 = __uint_as_float(pw.y & 0xFFFF0000u);
                float p4 = __uint_as_float(pw.z << 16), p5 = __uint_as_float(pw.z & 0xFFFF0000u);
                float p6 = __uint_as_float(pw.w << 16), p7 = __uint_as_float(pw.w & 0xFFFF0000u);
                float e0_ = __expf(p0*v0.x*ci[0]); float e1_ = __expf(p1*v0.y*ci[1]);
                float e2_ = __expf(p2*v0.z*ci[2]); float e3_ = __expf(p3*v0.w*ci[3]);
                float e4_ = __expf(p4*v1.x*ci[4]); float e5_ = __expf(p5*v1.y*ci[5]);
                float e6_ = __expf(p6*v1.z*ci[6]); float e7_ = __expf(p7*v1.w*ci[7]);
                z[0]+=e0_; z[1]+=e1_; z[2]+=e2_; z[3]+=e3_;
                z[4]+=e4_; z[5]+=e5_; z[6]+=e6_; z[7]+=e7_;
                float4 w0 = { t32(e0_), t32(e1_), t32(e2_), t32(e3_) };
                float4 w1 = { t32(e4_), t32(e5_), t32(e6_), t32(e7_) };
                *reinterpret_cast<float4*>(bsb + kr*544 + cq*32)      = w0;
                *reinterpret_cast<float4*>(bsb + kr*544 + cq*32 + 16) = w1;
            }
        }
        __syncthreads();
        if (ch + 1 < 32)
            kv_stage(su, cur ^ 1, A, PK, PV, (size_t)(ch + 1)*32, tid, cq, rb);
        // math: tf32 MMA, A frags from bf16 (exact <<16)
        {
            char* asb = smc + KVB_AS + cur*AS_S;
            char* bsb = smc + KVB_BS + cur*BS_S;
            #pragma unroll
            for (int kss = 0; kss < 4; kss++){
                const int kb = kss*8;
                uint32_t a[2][4], bf[8][2];
                #pragma unroll
                for (int mf = 0; mf < 2; mf++){
                    int row = wm*32 + mf*16 + g;
                    a[mf][0] = ((uint32_t)*reinterpret_cast<uint16_t*>(asb + ((kb+c4  )*PA1H + row  )*2)) << 16;
                    a[mf][1] = ((uint32_t)*reinterpret_cast<uint16_t*>(asb + ((kb+c4  )*PA1H + row+8)*2)) << 16;
                    a[mf][2] = ((uint32_t)*reinterpret_cast<uint16_t*>(asb + ((kb+c4+4)*PA1H + row  )*2)) << 16;
                    a[mf][3] = ((uint32_t)*reinterpret_cast<uint16_t*>(asb + ((kb+c4+4)*PA1H + row+8)*2)) << 16;
                }
                #pragma unroll
                for (int nf = 0; nf < 8; nf++){
                    int ncol = wn*64 + nf*8 + g;
                    bf[nf][0] = *reinterpret_cast<uint32_t*>(bsb + ((kb+c4  )*PB + ncol)*4);
                    bf[nf][1] = *reinterpret_cast<uint32_t*>(bsb + ((kb+c4+4)*PB + ncol)*4);
                }
                #pragma unroll
                for (int mf = 0; mf < 2; mf++)
                    #pragma unroll
                    for (int nf = 0; nf < 8; nf++)
                        mma8(acc[mf][nf], a[mf], bf[nf]);
            }
        }
    }

    __syncthreads();
    #pragma unroll
    for (int j = 0; j < 8; j++) zsm[rb*128 + cq*8 + j] = z[j];
    __syncthreads();
    if (blockIdx.y == 0 && tid < 128){
        float Z = 0.f;
        #pragma unroll
        for (int w = 0; w < 16; w++) Z += zsm[w*128 + tid];
        g_zpart[(b*4 + ks)*DD + e0 + tid] = Z;
    }

    float* part = g_kvpart + (size_t)(ks*BB + b)*DD*DD;
    #pragma unroll
    for (int mf = 0; mf < 2; mf++){
        int row = d0 + wm*32 + mf*16 + g;
        #pragma unroll
        for (int nf = 0; nf < 8; nf++){
            int col = e0 + wn*64 + nf*8 + c4*2;
            float2 r0 = { acc[mf][nf][0], acc[mf][nf][1] };
            float2 r1 = { acc[mf][nf][2], acc[mf][nf][3] };
            *reinterpret_cast<float2*>(part + (size_t)row*DD + col)     = r0;
            *reinterpret_cast<float2*>(part + (size_t)(row+8)*DD + col) = r1;
        }
    }
}

// ============ k_kvscaleT: kvT[e][d] = bf16( (Σ ks parts[d][e]) / Z[e] ) ============
__global__ __launch_bounds__(256) void k_kvscaleT(){
    __shared__ float t[32][33];
    __shared__ float zc[32];
    const int d0 = blockIdx.x*32, e0t = blockIdx.y*32, b = blockIdx.z;
    const int tx = threadIdx.x & 31, ty = threadIdx.x >> 5;
    const size_t S = (size_t)BB*DD*DD;
    if (ty == 0){
        int zb = b*4*DD + e0t + tx;
        zc[tx] = ((g_zpart[zb] + g_zpart[zb+DD]) + (g_zpart[zb+2*DD] + g_zpart[zb+3*DD]));
    }
    for (int i = ty; i < 32; i += 8){
        size_t idx = (size_t)b*DD*DD + (size_t)(d0+i)*DD + e0t + tx;
        t[i][tx] = ((g_kvpart[idx] + g_kvpart[idx+S]) + (g_kvpart[idx+2*S] + g_kvpart[idx+3*S]));
    }
    __syncthreads();
    unsigned short* o = g_kvT + (size_t)b*DD*DD;
    for (int i = ty; i < 32; i += 8){
        float v = t[tx][i] / zc[i];
        unsigned short h; asm("cvt.rn.bf16.f32 %0, %1;" : "=h"(h) : "f"(v));
        o[(size_t)(e0t+i)*DD + d0 + tx] = h;
    }
}

// ================= k_out: bf16 m16n8k16, R = gate * (phi_q @ KV) =================
#define PAOH 56                 // halfs pad (112B rows)
#define OA_S (128*PAOH*2)       // 14336
#define OB_S (128*PAOH*2)
#define OUT_STAGE (OA_S + OB_S) // 28672
#define SMEM_OUT (2*OUT_STAGE)  // 57344

__device__ __forceinline__ void out_stage(uint32_t su, int buf, const unsigned short* A,
                                          const unsigned short* B, int ch, int tid){
    uint32_t base = su + (uint32_t)(buf*OUT_STAGE);
    #pragma unroll
    for (int i = 0; i < 2; i++){
        int idx = tid + i*256;
        int m = idx >> 2, kq = idx & 3;
        cpa16(base + (uint32_t)(m*112 + kq*16), A + (size_t)m*DD + ch*32 + kq*8);
    }
    uint32_t bbase = base + OA_S;
    #pragma unroll
    for (int i = 0; i < 2; i++){
        int idx = tid + i*256;
        int n = idx >> 2, kq = idx & 3;
        cpa16(bbase + (uint32_t)(n*112 + kq*16), B + (size_t)n*DD + ch*32 + kq*8);
    }
    CP_COMMIT();
}

__global__ __launch_bounds__(256, 2) void k_out(float* __restrict__ out){
    extern __shared__ char smc[];
    uint32_t su = smem_u32(smc);
    const int m0 = blockIdx.y * 128, e0 = blockIdx.x * 128;
    const int b = m0 >> 12;
    const unsigned short* A = g_phiq + (size_t)m0*DD;
    const unsigned short* B = g_kvT + (size_t)b*DD*DD + (size_t)e0*DD;
    const int tid = threadIdx.x, lane = tid & 31, wid = tid >> 5;
    const int wm = wid & 3, wn = wid >> 2, g = lane >> 2, c4 = lane & 3;

    float acc[2][8][4];
    #pragma unroll
    for (int mf = 0; mf < 2; mf++)
        #pragma unroll
        for (int nf = 0; nf < 8; nf++)
            #pragma unroll
            for (int j = 0; j < 4; j++) acc[mf][nf][j] = 0.f;

    out_stage(su, 0, A, B, 0, tid);
    for (int ch = 0; ch < 8; ch++){
        const int cur = ch & 1;
        CP_WAIT0();
        __syncthreads();
        if (ch + 1 < 8) out_stage(su, cur ^ 1, A, B, ch + 1, tid);
        char* asb = smc + cur*OUT_STAGE;
        char* bsb = smc + cur*OUT_STAGE + OA_S;
        #pragma unroll
        for (int ks2 = 0; ks2 < 2; ks2++){
            const int kb = ks2*16;
            uint32_t a[2][4], bf[8][2];
            #pragma unroll
            for (int mf = 0; mf < 2; mf++){
                int row = wm*32 + mf*16 + g;
                a[mf][0] = *reinterpret_cast<uint32_t*>(asb + (row  )*112 + (kb + 2*c4)*2);
                a[mf][1] = *reinterpret_cast<uint32_t*>(asb + (row+8)*112 + (kb + 2*c4)*2);
                a[mf][2] = *reinterpret_cast<uint32_t*>(asb + (row  )*112 + (kb + 2*c4)*2 + 16);
                a[mf][3] = *reinterpret_cast<uint32_t*>(asb + (row+8)*112 + (kb + 2*c4)*2 + 16);
            }
            #pragma unroll
            for (int nf = 0; nf < 8; nf++){
                int ncol = wn*64 + nf*8 + g;
                bf[nf][0] = *reinterpret_cast<uint32_t*>(bsb + ncol*112 + (kb + 2*c4)*2);
                bf[nf][1] = *reinterpret_cast<uint32_t*>(bsb + ncol*112 + (kb + 2*c4)*2 + 16);
            }
            #pragma unroll
            for (int mf = 0; mf < 2; mf++)
                #pragma unroll
                for (int nf = 0; nf < 8; nf++)
                    mma16(acc[mf][nf], a[mf], bf[nf]);
        }
    }

    #pragma unroll
    for (int mf = 0; mf < 2; mf++){
        int row = m0 + wm*32 + mf*16 + g;
        float rs0 = g_rowpart[row]   + g_rowpart[BN_TOT + row];
        float rs1 = g_rowpart[row+8] + g_rowpart[BN_TOT + row + 8];
        float sc0 = sigf(rs0) / (rs0 + EPSF);
        float sc1 = sigf(rs1) / (rs1 + EPSF);
        #pragma unroll
        for (int nf = 0; nf < 8; nf++){
            int col = e0 + wn*64 + nf*8 + c4*2;
            float2 r0 = { acc[mf][nf][0]*sc0, acc[mf][nf][1]*sc0 };
            float2 r1 = { acc[mf][nf][2]*sc1, acc[mf][nf][3]*sc1 };
            *reinterpret_cast<float2*>(out + (size_t)row*DD + col)     = r0;
            *reinterpret_cast<float2*>(out + (size_t)(row+8)*DD + col) = r1;
        }
    }
}

// ================= launch =================
extern "C" void kernel_launch(void* const* d_in, const int* in_sizes, int n_in,
                              void* d_out, int out_size){
    const float* Q  = (const float*)d_in[0];
    const float* K  = (const float*)d_in[1];
    const float* V  = (const float*)d_in[2];
    const float* Wq = (const float*)d_in[3];
    const float* bq = (const float*)d_in[4];
    const float* Wk = (const float*)d_in[5];
    const float* bk = (const float*)d_in[6];
    float* out = (float*)d_out;
    (void)in_sizes; (void)n_in; (void)out_size;

    cudaFuncSetAttribute(k_phi, cudaFuncAttributeMaxDynamicSharedMemorySize, SMEM_DB);
    cudaFuncSetAttribute(k_kv,  cudaFuncAttributeMaxDynamicSharedMemorySize, SMEM_KV);
    cudaFuncSetAttribute(k_out, cudaFuncAttributeMaxDynamicSharedMemorySize, SMEM_OUT);

    k_phi<<<dim3(2,512), 256, SMEM_DB>>>(Q, Wq, bq, 0);   // phi_q bf16 + rowsum partials
    k_phi<<<dim3(2,512), 256, SMEM_DB>>>(K, Wk, bk, 1);   // phi_k bf16 + colsum partials
    k_colsum<<<16, 256>>>();
    k_kv<<<dim3(2,2,BB*4), 256, SMEM_KV>>>(V);            // KV' partials + Z, 2 CTA/SM
    k_kvscaleT<<<dim3(8,8,BB), 256>>>();                  // combine, /Z, transpose -> bf16
    k_out<<<dim3(2,512), 256, SMEM_OUT>>>(out);           // final R (bf16 MMA)
}

// round 12
// speedup vs baseline: 1.6402x; 1.1356x over previous
#include <cuda_runtime.h>
#include <cstdint>

#define BB 16
#define NN 4096
#define DD 256
#define BN_TOT (BB*NN)          // 65536
#define EPSF 1e-6f

// ---------------- scratch ----------------
__device__ unsigned short g_phiq[BN_TOT*DD];   // [bn][d] bf16, 32MB
__device__ unsigned short g_phik[BN_TOT*DD];   // [bn][d] bf16, 32MB
__device__ float g_rowpart[2*BN_TOT];
__device__ float g_colpart2[BB*32*DD];
__device__ float g_colsum[BB*DD];
__device__ float g_zpart[BB*4*DD];             // Z partials per ks (4)
__device__ float g_kvpart[4*BB*DD*DD];         // split-K KV partials [d][e]
__device__ unsigned short g_kvT[BB*DD*DD];     // bf16, TRANSPOSED [b][e][d]

__device__ __forceinline__ float sigf(float x){ return 1.0f/(1.0f + __expf(-x)); }
__device__ __forceinline__ float t32(float a){
    uint32_t u; asm("cvt.rna.tf32.f32 %0, %1;" : "=r"(u) : "f"(a)); return __uint_as_float(u);
}
__device__ __forceinline__ uint32_t pack_bf2(float lo, float hi){
    uint32_t r; asm("cvt.rn.bf16x2.f32 %0, %1, %2;" : "=r"(r) : "f"(hi), "f"(lo)); return r;
}
__device__ __forceinline__ void mma8(float* d, const uint32_t* a, const uint32_t* b){
    asm volatile("mma.sync.aligned.m16n8k8.row.col.f32.tf32.tf32.f32 "
        "{%0,%1,%2,%3}, {%4,%5,%6,%7}, {%8,%9}, {%0,%1,%2,%3};"
        : "+f"(d[0]), "+f"(d[1]), "+f"(d[2]), "+f"(d[3])
        : "r"(a[0]), "r"(a[1]), "r"(a[2]), "r"(a[3]), "r"(b[0]), "r"(b[1]));
}
__device__ __forceinline__ void mma16(float* d, const uint32_t* a, const uint32_t* b){
    asm volatile("mma.sync.aligned.m16n8k16.row.col.f32.bf16.bf16.f32 "
        "{%0,%1,%2,%3}, {%4,%5,%6,%7}, {%8,%9}, {%0,%1,%2,%3};"
        : "+f"(d[0]), "+f"(d[1]), "+f"(d[2]), "+f"(d[3])
        : "r"(a[0]), "r"(a[1]), "r"(a[2]), "r"(a[3]), "r"(b[0]), "r"(b[1]));
}
__device__ __forceinline__ void ldsm4t(uint32_t& r0, uint32_t& r1, uint32_t& r2, uint32_t& r3,
                                       uint32_t addr){
    asm volatile("ldmatrix.sync.aligned.m8n8.x4.trans.shared.b16 {%0,%1,%2,%3}, [%4];"
        : "=r"(r0), "=r"(r1), "=r"(r2), "=r"(r3) : "r"(addr));
}
__device__ __forceinline__ uint32_t smem_u32(const void* p){
    uint32_t a; asm("{ .reg .u64 t; cvta.to.shared.u64 t, %1; cvt.u32.u64 %0, t; }" : "=r"(a) : "l"(p));
    return a;
}
__device__ __forceinline__ void cpa16(uint32_t saddr, const void* g){
    asm volatile("cp.async.ca.shared.global [%0], [%1], 16;" :: "r"(saddr), "l"(g));
}
#define CP_COMMIT() asm volatile("cp.async.commit_group;" ::: "memory")
#define CP_WAIT0()  asm volatile("cp.async.wait_group 0;" ::: "memory")

// ================= tf32 core (k_phi): 256 thr, 128x128, BK=32 =================
#define PA0 36
#define PB  136
#define A_FL (128*PA0)
#define B_FL (32*PB)
#define STAGE_FL (A_FL + B_FL)          // 8960 floats
#define SMEM_DB (2*STAGE_FL*4)          // 71680

__device__ __forceinline__ void math_chunk0(const float* As, const float* Bs, float acc[2][8][4],
                                            int wm, int wn, int g, int c4){
    #pragma unroll
    for (int ks = 0; ks < 4; ks++){
        const int kb = ks*8;
        uint32_t a[2][4], bf[8][2];
        #pragma unroll
        for (int mf = 0; mf < 2; mf++){
            int row = wm*32 + mf*16 + g;
            a[mf][0] = __float_as_uint(As[(row  )*PA0 + kb + c4    ]);
            a[mf][1] = __float_as_uint(As[(row+8)*PA0 + kb + c4    ]);
            a[mf][2] = __float_as_uint(As[(row  )*PA0 + kb + c4 + 4]);
            a[mf][3] = __float_as_uint(As[(row+8)*PA0 + kb + c4 + 4]);
        }
        #pragma unroll
        for (int nf = 0; nf < 8; nf++){
            int ncol = wn*64 + nf*8 + g;
            bf[nf][0] = __float_as_uint(Bs[(kb+c4  )*PB + ncol]);
            bf[nf][1] = __float_as_uint(Bs[(kb+c4+4)*PB + ncol]);
        }
        #pragma unroll
        for (int mf = 0; mf < 2; mf++)
            #pragma unroll
            for (int nf = 0; nf < 8; nf++)
                mma8(acc[mf][nf], a[mf], bf[nf]);
    }
}

__device__ __forceinline__ void stage_async(uint32_t su, int s, const float* A, int lda,
                                            const float* B, int ldb, int ch, int tid){
    uint32_t base = su + (uint32_t)(s*STAGE_FL*4);
    #pragma unroll
    for (int i = 0; i < 4; i++){
        int idx = tid + i*256;
        int m = idx >> 3, kq = idx & 7;
        cpa16(base + (uint32_t)(m*PA0 + kq*4)*4, A + (size_t)m*lda + ch*32 + kq*4);
    }
    uint32_t bbase = base + A_FL*4;
    #pragma unroll
    for (int i = 0; i < 4; i++){
        int idx = tid + i*256;
        int kr = idx >> 5, nq = idx & 31;
        cpa16(bbase + (uint32_t)(kr*PB + nq*4)*4, B + (size_t)(ch*32 + kr)*ldb + nq*4);
    }
    CP_COMMIT();
}

__device__ __forceinline__ void convert_stage(float* sm, int s, int tid){
    float* base = sm + s*STAGE_FL;
    #pragma unroll
    for (int i = 0; i < 4; i++){
        int idx = tid + i*256;
        int m = idx >> 3, kq = idx & 7;
        float4* p = reinterpret_cast<float4*>(base + m*PA0 + kq*4);
        float4 v = *p;
        v.x=t32(v.x); v.y=t32(v.y); v.z=t32(v.z); v.w=t32(v.w);
        *p = v;
    }
    float* bb = base + A_FL;
    #pragma unroll
    for (int i = 0; i < 4; i++){
        int idx = tid + i*256;
        int kr = idx >> 5, nq = idx & 31;
        float4* p = reinterpret_cast<float4*>(bb + kr*PB + nq*4);
        float4 v = *p;
        v.x=t32(v.x); v.y=t32(v.y); v.z=t32(v.z); v.w=t32(v.w);
        *p = v;
    }
}

__device__ __forceinline__ void gemm_async(const float* A, int lda, const float* B, int ldb,
                                           int kchunks, float acc[2][8][4], float* sm, uint32_t su){
    const int tid = threadIdx.x, lane = tid & 31, wid = tid >> 5;
    const int wm = wid & 3, wn = wid >> 2, g = lane >> 2, c4 = lane & 3;
    #pragma unroll
    for (int mf = 0; mf < 2; mf++)
        #pragma unroll
        for (int nf = 0; nf < 8; nf++)
            #pragma unroll
            for (int j = 0; j < 4; j++) acc[mf][nf][j] = 0.f;

    stage_async(su, 0, A, lda, B, ldb, 0, tid);
    for (int ch = 0; ch < kchunks; ch++){
        int cur = ch & 1;
        CP_WAIT0();
        convert_stage(sm, cur, tid);
        __syncthreads();
        if (ch + 1 < kchunks)
            stage_async(su, cur ^ 1, A, lda, B, ldb, ch + 1, tid);
        math_chunk0(sm + cur*STAGE_FL, sm + cur*STAGE_FL + A_FL, acc, wm, wn, g, c4);
    }
    __syncthreads();
}

// ================= k_phi: phi = sigmoid(X @ W + b) -> bf16, fused reductions ======
__global__ __launch_bounds__(256, 2) void k_phi(const float* __restrict__ X,
                                                const float* __restrict__ W,
                                                const float* __restrict__ bias, int which){
    extern __shared__ float sm[];
    uint32_t su = smem_u32(sm);
    unsigned short* out = which ? g_phik : g_phiq;
    const int m0 = blockIdx.y * 128, e0 = blockIdx.x * 128;
    float acc[2][8][4];
    gemm_async(X + (size_t)m0*DD, DD, W + e0, DD, 8, acc, sm, su);

    const int tid = threadIdx.x, lane = tid & 31, wid = tid >> 5;
    const int wm = wid & 3, wn = wid >> 2, g = lane >> 2, c4 = lane & 3;

    float rpart[2][2] = {{0.f,0.f},{0.f,0.f}};
    float cpart[8][2];
    #pragma unroll
    for (int nf = 0; nf < 8; nf++){ cpart[nf][0]=0.f; cpart[nf][1]=0.f; }

    #pragma unroll
    for (int mf = 0; mf < 2; mf++){
        int row = m0 + wm*32 + mf*16 + g;
        #pragma unroll
        for (int nf = 0; nf < 8; nf++){
            int lcol = wn*64 + nf*8 + c4*2;
            float b0 = bias[e0 + lcol], b1 = bias[e0 + lcol + 1];
            float s00 = sigf(acc[mf][nf][0] + b0), s01 = sigf(acc[mf][nf][1] + b1);
            float s10 = sigf(acc[mf][nf][2] + b0), s11 = sigf(acc[mf][nf][3] + b1);
            *reinterpret_cast<uint32_t*>(out + (size_t)row*DD + e0 + lcol)     = pack_bf2(s00, s01);
            *reinterpret_cast<uint32_t*>(out + (size_t)(row+8)*DD + e0 + lcol) = pack_bf2(s10, s11);
            rpart[mf][0] += s00 + s01;
            rpart[mf][1] += s10 + s11;
            cpart[nf][0] += s00 + s10;
            cpart[nf][1] += s01 + s11;
        }
    }
    __syncthreads();

    if (!which){
        #pragma unroll
        for (int mf = 0; mf < 2; mf++)
            #pragma unroll
            for (int h = 0; h < 2; h++){
                rpart[mf][h] += __shfl_xor_sync(0xffffffffu, rpart[mf][h], 1);
                rpart[mf][h] += __shfl_xor_sync(0xffffffffu, rpart[mf][h], 2);
            }
        if (c4 == 0){
            #pragma unroll
            for (int mf = 0; mf < 2; mf++){
                int r = wm*32 + mf*16 + g;
                sm[wn*128 + r]     = rpart[mf][0];
                sm[wn*128 + r + 8] = rpart[mf][1];
            }
        }
        __syncthreads();
        if (tid < 128)
            g_rowpart[(size_t)blockIdx.x*BN_TOT + m0 + tid] = sm[tid] + sm[128 + tid];
    } else {
        #pragma unroll
        for (int nf = 0; nf < 8; nf++)
            #pragma unroll
            for (int h = 0; h < 2; h++){
                cpart[nf][h] += __shfl_xor_sync(0xffffffffu, cpart[nf][h], 4);
                cpart[nf][h] += __shfl_xor_sync(0xffffffffu, cpart[nf][h], 8);
                cpart[nf][h] += __shfl_xor_sync(0xffffffffu, cpart[nf][h], 16);
            }
        if (g == 0){
            #pragma unroll
            for (int nf = 0; nf < 8; nf++){
                int lcol = wn*64 + nf*8 + c4*2;
                sm[wm*128 + lcol]     = cpart[nf][0];
                sm[wm*128 + lcol + 1] = cpart[nf][1];
            }
        }
        __syncthreads();
        if (tid < 128){
            float s = ((sm[tid] + sm[128+tid]) + (sm[256+tid] + sm[384+tid]));
            int b = m0 >> 12, mt = (m0 >> 7) & 31;
            g_colpart2[((b*32 + mt) << 8) + e0 + tid] = s;
        }
    }
}

// ================= k_colsum =================
__global__ __launch_bounds__(256) void k_colsum(){
    int idx = blockIdx.x*256 + threadIdx.x;
    int b = idx >> 8, d = idx & 255;
    float s = 0.f;
    #pragma unroll
    for (int mt = 0; mt < 32; mt++) s += g_colpart2[((b*32+mt)<<8) + d];
    g_colsum[idx] = s;
}

// ================= k_kv: bf16 mma16 + ldmatrix + Taylor-exp =====================
#define AS_S 8704               // 32*136 bf16 bytes
#define BS_S 8704               // 32*136 bf16 bytes
#define PK_S 8192               // 32*128 bf16 bytes
#define PV_S 16384              // 32*128 fp32 bytes
#define KVB_AS 0
#define KVB_BS (2*AS_S)         // 17408
#define KVB_PK (KVB_BS + 2*BS_S)// 34816
#define KVB_PV (KVB_PK + 2*PK_S)// 51200
#define SMEM_KV (KVB_PV + 2*PV_S)// 83968
#define PA1H 136

__device__ __forceinline__ void kv_stage(uint32_t su, int buf,
                                         const unsigned short* A, const unsigned short* PK,
                                         const float* PV, size_t roff, int tid, int cq, int rb){
    #pragma unroll
    for (int i = 0; i < 2; i++){
        int idx = tid + i*256;
        int kr = idx >> 4, dq = idx & 15;
        cpa16(su + KVB_AS + (uint32_t)(buf*AS_S + kr*272 + dq*16), A + (roff+kr)*DD + dq*8);
    }
    #pragma unroll
    for (int r = 0; r < 2; r++){
        int kr = rb + r*16;
        cpa16(su + KVB_PK + (uint32_t)(buf*PK_S + kr*256 + cq*16),      PK + (roff+kr)*DD + cq*8);
        cpa16(su + KVB_PV + (uint32_t)(buf*PV_S + kr*512 + cq*32),      PV + (roff+kr)*DD + cq*8);
        cpa16(su + KVB_PV + (uint32_t)(buf*PV_S + kr*512 + cq*32 + 16), PV + (roff+kr)*DD + cq*8 + 4);
    }
    CP_COMMIT();
}

__global__ __launch_bounds__(256, 2) void k_kv(const float* __restrict__ V){
    extern __shared__ char smc[];
    uint32_t su = smem_u32(smc);
    __shared__ float cinvs[128];
    __shared__ float zsm[16*128];
    const int tid = threadIdx.x, lane = tid & 31, wid = tid >> 5;
    const int wm = wid & 3, wn = wid >> 2, g = lane >> 2, c4 = lane & 3;
    const int e0 = blockIdx.x * 128, d0 = blockIdx.y * 128;
    const int b = blockIdx.z >> 2, ks = blockIdx.z & 3;
    const unsigned short* A  = g_phik + (size_t)(b*NN + ks*1024)*DD + d0;
    const unsigned short* PK = g_phik + (size_t)(b*NN + ks*1024)*DD + e0;
    const float* PV = V + (size_t)(b*NN + ks*1024)*DD + e0;

    if (tid < 128) cinvs[tid] = 1.0f/(g_colsum[b*DD + e0 + tid] + EPSF);

    float acc[2][8][4];
    #pragma unroll
    for (int mf = 0; mf < 2; mf++)
        #pragma unroll
        for (int nf = 0; nf < 8; nf++)
            #pragma unroll
            for (int j = 0; j < 4; j++) acc[mf][nf][j] = 0.f;

    const int cq = tid & 15;     // 8-col group
    const int rb = tid >> 4;     // rows rb, rb+16
    float z[8] = {0.f,0.f,0.f,0.f,0.f,0.f,0.f,0.f};

    // ldmatrix per-lane address components
    const int akrow = (lane & 7) + ((lane & 16) >> 1);   // A: k row within chunk
    const int amcol = (lane & 8);                        // A: m col offset
    const int bkrow = (lane & 7) + (lane & 8);           // B: k row within chunk
    const int bncol = ((lane & 16) >> 1);                // B: n col offset

    kv_stage(su, 0, A, PK, PV, 0, tid, cq, rb);
    __syncthreads();
    float ci[8];
    #pragma unroll
    for (int j = 0; j < 8; j++) ci[j] = cinvs[cq*8 + j];

    for (int ch = 0; ch < 32; ch++){
        const int cur = ch & 1;
        CP_WAIT0();
        // exp phase (Taylor: |s|<~0.01 so 1+s+s^2/2 is exact to ~1e-8): own-staged bytes only
        {
            char* pkb = smc + KVB_PK + cur*PK_S;
            char* pvb = smc + KVB_PV + cur*PV_S;
            char* bsb = smc + KVB_BS + cur*BS_S;
            #pragma unroll
            for (int r = 0; r < 2; r++){
                int kr = rb + r*16;
                uint4  pw = *reinterpret_cast<uint4*>(pkb + kr*256 + cq*16);
                float4 v0 = *reinterpret_cast<float4*>(pvb + kr*512 + cq*32);
                float4 v1 = *reinterpret_cast<float4*>(pvb + kr*512 + cq*32 + 16);
                float p0 = __uint_as_float(pw.x << 16), p1 = __uint_as_float(pw.x & 0xFFFF0000u);
                float p2 = __uint_as_float(pw.y << 16), p3 = __uint_as_float(pw.y & 0xFFFF0000u);
                float p4 = __uint_as_float(pw.z << 16), p5 = __uint_as_float(pw.z & 0xFFFF0000u);
                float p6 = __uint_as_float(pw.w << 16), p7 = __uint_as_float(pw.w & 0xFFFF0000u);
                float s0 = p0*v0.x*ci[0], s1 = p1*v0.y*ci[1];
                float s2 = p2*v0.z*ci[2], s3 = p3*v0.w*ci[3];
                float s4 = p4*v1.x*ci[4], s5 = p5*v1.y*ci[5];
                float s6 = p6*v1.z*ci[6], s7 = p7*v1.w*ci[7];
                float e0_ = 1.f + s0*(1.f + 0.5f*s0);
                float e1_ = 1.f + s1*(1.f + 0.5f*s1);
                float e2_ = 1.f + s2*(1.f + 0.5f*s2);
                float e3_ = 1.f + s3*(1.f + 0.5f*s3);
                float e4_ = 1.f + s4*(1.f + 0.5f*s4);
                float e5_ = 1.f + s5*(1.f + 0.5f*s5);
                float e6_ = 1.f + s6*(1.f + 0.5f*s6);
                float e7_ = 1.f + s7*(1.f + 0.5f*s7);
                z[0]+=e0_; z[1]+=e1_; z[2]+=e2_; z[3]+=e3_;
                z[4]+=e4_; z[5]+=e5_; z[6]+=e6_; z[7]+=e7_;
                uint4 w;
                w.x = pack_bf2(e0_, e1_);
                w.y = pack_bf2(e2_, e3_);
                w.z = pack_bf2(e4_, e5_);
                w.w = pack_bf2(e6_, e7_);
                *reinterpret_cast<uint4*>(bsb + kr*272 + cq*16) = w;
            }
        }
        __syncthreads();
        if (ch + 1 < 32)
            kv_stage(su, cur ^ 1, A, PK, PV, (size_t)(ch + 1)*32, tid, cq, rb);
        // math: bf16 mma16, frags via ldmatrix.x4.trans
        {
            uint32_t abase = su + KVB_AS + (uint32_t)(cur*AS_S);
            uint32_t bbase = su + KVB_BS + (uint32_t)(cur*BS_S);
            #pragma unroll
            for (int ks2 = 0; ks2 < 2; ks2++){
                const int kb = ks2*16;
                uint32_t a[2][4];
                #pragma unroll
                for (int mf = 0; mf < 2; mf++){
                    uint32_t ad = abase + (uint32_t)((kb + akrow)*PA1H + wm*32 + mf*16 + amcol)*2;
                    ldsm4t(a[mf][0], a[mf][1], a[mf][2], a[mf][3], ad);
                }
                #pragma unroll
                for (int nf2 = 0; nf2 < 4; nf2++){
                    uint32_t r0, r1, r2, r3;
                    uint32_t bd = bbase + (uint32_t)((kb + bkrow)*PB + wn*64 + nf2*16 + bncol)*2;
                    ldsm4t(r0, r1, r2, r3, bd);
                    uint32_t b0[2] = { r0, r1 };
                    uint32_t b1[2] = { r2, r3 };
                    #pragma unroll
                    for (int mf = 0; mf < 2; mf++){
                        mma16(acc[mf][nf2*2 + 0], a[mf], b0);
                        mma16(acc[mf][nf2*2 + 1], a[mf], b1);
                    }
                }
            }
        }
    }

    __syncthreads();
    #pragma unroll
    for (int j = 0; j < 8; j++) zsm[rb*128 + cq*8 + j] = z[j];
    __syncthreads();
    if (blockIdx.y == 0 && tid < 128){
        float Z = 0.f;
        #pragma unroll
        for (int w = 0; w < 16; w++) Z += zsm[w*128 + tid];
        g_zpart[(b*4 + ks)*DD + e0 + tid] = Z;
    }

    float* part = g_kvpart + (size_t)(ks*BB + b)*DD*DD;
    #pragma unroll
    for (int mf = 0; mf < 2; mf++){
        int row = d0 + wm*32 + mf*16 + g;
        #pragma unroll
        for (int nf = 0; nf < 8; nf++){
            int col = e0 + wn*64 + nf*8 + c4*2;
            float2 r0 = { acc[mf][nf][0], acc[mf][nf][1] };
            float2 r1 = { acc[mf][nf][2], acc[mf][nf][3] };
            *reinterpret_cast<float2*>(part + (size_t)row*DD + col)     = r0;
            *reinterpret_cast<float2*>(part + (size_t)(row+8)*DD + col) = r1;
        }
    }
}

// ============ k_kvscaleT: kvT[e][d] = bf16( (Σ ks parts[d][e]) / Z[e] ) ============
__global__ __launch_bounds__(256) void k_kvscaleT(){
    __shared__ float t[32][33];
    __shared__ float zc[32];
    const int d0 = blockIdx.x*32, e0t = blockIdx.y*32, b = blockIdx.z;
    const int tx = threadIdx.x & 31, ty = threadIdx.x >> 5;
    const size_t S = (size_t)BB*DD*DD;
    if (ty == 0){
        int zb = b*4*DD + e0t + tx;
        zc[tx] = ((g_zpart[zb] + g_zpart[zb+DD]) + (g_zpart[zb+2*DD] + g_zpart[zb+3*DD]));
    }
    for (int i = ty; i < 32; i += 8){
        size_t idx = (size_t)b*DD*DD + (size_t)(d0+i)*DD + e0t + tx;
        t[i][tx] = ((g_kvpart[idx] + g_kvpart[idx+S]) + (g_kvpart[idx+2*S] + g_kvpart[idx+3*S]));
    }
    __syncthreads();
    unsigned short* o = g_kvT + (size_t)b*DD*DD;
    for (int i = ty; i < 32; i += 8){
        float v = t[tx][i] / zc[i];
        unsigned short h; asm("cvt.rn.bf16.f32 %0, %1;" : "=h"(h) : "f"(v));
        o[(size_t)(e0t+i)*DD + d0 + tx] = h;
    }
}

// ================= k_out: bf16 m16n8k16, R = gate * (phi_q @ KV) =================
#define PAOH 56                 // halfs pad (112B rows)
#define OA_S (128*PAOH*2)       // 14336
#define OB_S (128*PAOH*2)
#define OUT_STAGE (OA_S + OB_S) // 28672
#define SMEM_OUT (2*OUT_STAGE)  // 57344

__device__ __forceinline__ void out_stage(uint32_t su, int buf, const unsigned short* A,
                                          const unsigned short* B, int ch, int tid){
    uint32_t base = su + (uint32_t)(buf*OUT_STAGE);
    #pragma unroll
    for (int i = 0; i < 2; i++){
        int idx = tid + i*256;
        int m = idx >> 2, kq = idx & 3;
        cpa16(base + (uint32_t)(m*112 + kq*16), A + (size_t)m*DD + ch*32 + kq*8);
    }
    uint32_t bbase = base + OA_S;
    #pragma unroll
    for (int i = 0; i < 2; i++){
        int idx = tid + i*256;
        int n = idx >> 2, kq = idx & 3;
        cpa16(bbase + (uint32_t)(n*112 + kq*16), B + (size_t)n*DD + ch*32 + kq*8);
    }
    CP_COMMIT();
}

__global__ __launch_bounds__(256, 2) void k_out(float* __restrict__ out){
    extern __shared__ char smc[];
    uint32_t su = smem_u32(smc);
    const int m0 = blockIdx.y * 128, e0 = blockIdx.x * 128;
    const int b = m0 >> 12;
    const unsigned short* A = g_phiq + (size_t)m0*DD;
    const unsigned short* B = g_kvT + (size_t)b*DD*DD + (size_t)e0*DD;
    const int tid = threadIdx.x, lane = tid & 31, wid = tid >> 5;
    const int wm = wid & 3, wn = wid >> 2, g = lane >> 2, c4 = lane & 3;

    float acc[2][8][4];
    #pragma unroll
    for (int mf = 0; mf < 2; mf++)
        #pragma unroll
        for (int nf = 0; nf < 8; nf++)
            #pragma unroll
            for (int j = 0; j < 4; j++) acc[mf][nf][j] = 0.f;

    out_stage(su, 0, A, B, 0, tid);
    for (int ch = 0; ch < 8; ch++){
        const int cur = ch & 1;
        CP_WAIT0();
        __syncthreads();
        if (ch + 1 < 8) out_stage(su, cur ^ 1, A, B, ch + 1, tid);
        char* asb = smc + cur*OUT_STAGE;
        char* bsb = smc + cur*OUT_STAGE + OA_S;
        #pragma unroll
        for (int ks2 = 0; ks2 < 2; ks2++){
            const int kb = ks2*16;
            uint32_t a[2][4], bf[8][2];
            #pragma unroll
            for (int mf = 0; mf < 2; mf++){
                int row = wm*32 + mf*16 + g;
                a[mf][0] = *reinterpret_cast<uint32_t*>(asb + (row  )*112 + (kb + 2*c4)*2);
                a[mf][1] = *reinterpret_cast<uint32_t*>(asb + (row+8)*112 + (kb + 2*c4)*2);
                a[mf][2] = *reinterpret_cast<uint32_t*>(asb + (row  )*112 + (kb + 2*c4)*2 + 16);
                a[mf][3] = *reinterpret_cast<uint32_t*>(asb + (row+8)*112 + (kb + 2*c4)*2 + 16);
            }
            #pragma unroll
            for (int nf = 0; nf < 8; nf++){
                int ncol = wn*64 + nf*8 + g;
                bf[nf][0] = *reinterpret_cast<uint32_t*>(bsb + ncol*112 + (kb + 2*c4)*2);
                bf[nf][1] = *reinterpret_cast<uint32_t*>(bsb + ncol*112 + (kb + 2*c4)*2 + 16);
            }
            #pragma unroll
            for (int mf = 0; mf < 2; mf++)
                #pragma unroll
                for (int nf = 0; nf < 8; nf++)
                    mma16(acc[mf][nf], a[mf], bf[nf]);
        }
    }

    #pragma unroll
    for (int mf = 0; mf < 2; mf++){
        int row = m0 + wm*32 + mf*16 + g;
        float rs0 = g_rowpart[row]   + g_rowpart[BN_TOT + row];
        float rs1 = g_rowpart[row+8] + g_rowpart[BN_TOT + row + 8];
        float sc0 = sigf(rs0) / (rs0 + EPSF);
        float sc1 = sigf(rs1) / (rs1 + EPSF);
        #pragma unroll
        for (int nf = 0; nf < 8; nf++){
            int col = e0 + wn*64 + nf*8 + c4*2;
            float2 r0 = { acc[mf][nf][0]*sc0, acc[mf][nf][1]*sc0 };
            float2 r1 = { acc[mf][nf][2]*sc1, acc[mf][nf][3]*sc1 };
            *reinterpret_cast<float2*>(out + (size_t)row*DD + col)     = r0;
            *reinterpret_cast<float2*>(out + (size_t)(row+8)*DD + col) = r1;
        }
    }
}

// ================= launch =================
extern "C" void kernel_launch(void* const* d_in, const int* in_sizes, int n_in,
                              void* d_out, int out_size){
    const float* Q  = (const float*)d_in[0];
    const float* K  = (const float*)d_in[1];
    const float* V  = (const float*)d_in[2];
    const float* Wq = (const float*)d_in[3];
    const float* bq = (const float*)d_in[4];
    const float* Wk = (const float*)d_in[5];
    const float* bk = (const float*)d_in[6];
    float* out = (float*)d_out;
    (void)in_sizes; (void)n_in; (void)out_size;

    cudaFuncSetAttribute(k_phi, cudaFuncAttributeMaxDynamicSharedMemorySize, SMEM_DB);
    cudaFuncSetAttribute(k_kv,  cudaFuncAttributeMaxDynamicSharedMemorySize, SMEM_KV);
    cudaFuncSetAttribute(k_out, cudaFuncAttributeMaxDynamicSharedMemorySize, SMEM_OUT);

    k_phi<<<dim3(2,512), 256, SMEM_DB>>>(Q, Wq, bq, 0);   // phi_q bf16 + rowsum partials
    k_phi<<<dim3(2,512), 256, SMEM_DB>>>(K, Wk, bk, 1);   // phi_k bf16 + colsum partials
    k_colsum<<<16, 256>>>();
    k_kv<<<dim3(2,2,BB*4), 256, SMEM_KV>>>(V);            // KV' partials + Z (bf16 mma)
    k_kvscaleT<<<dim3(8,8,BB), 256>>>();                  // combine, /Z, transpose -> bf16
    k_out<<<dim3(2,512), 256, SMEM_OUT>>>(out);           // final R (bf16 MMA)
}

// round 14
// speedup vs baseline: 1.6635x; 1.0142x over previous
#include <cuda_runtime.h>
#include <cstdint>

#define BB 16
#define NN 4096
#define DD 256
#define BN_TOT (BB*NN)          // 65536
#define EPSF 1e-6f

// ---------------- scratch ----------------
__device__ unsigned short g_phiq[BN_TOT*DD];   // [bn][d] bf16, 32MB
__device__ unsigned short g_phik[BN_TOT*DD];   // [bn][d] bf16, 32MB
__device__ unsigned short g_Vbf [BN_TOT*DD];   // [bn][d] bf16, 32MB
__device__ float g_rowpart[2*BN_TOT];
__device__ float g_colpart2[BB*32*DD];
__device__ float g_colsum[BB*DD];
__device__ float g_zpart[BB*4*DD];             // Z partials per ks (4)
__device__ float g_kvpart[4*BB*DD*DD];         // split-K KV partials [d][e]
__device__ unsigned short g_kvT[BB*DD*DD];     // bf16, TRANSPOSED [b][e][d]

__device__ __forceinline__ float sigf(float x){ return 1.0f/(1.0f + __expf(-x)); }
__device__ __forceinline__ float t32(float a){
    uint32_t u; asm("cvt.rna.tf32.f32 %0, %1;" : "=r"(u) : "f"(a)); return __uint_as_float(u);
}
__device__ __forceinline__ uint32_t pack_bf2(float lo, float hi){
    uint32_t r; asm("cvt.rn.bf16x2.f32 %0, %1, %2;" : "=r"(r) : "f"(hi), "f"(lo)); return r;
}
__device__ __forceinline__ void mma8(float* d, const uint32_t* a, const uint32_t* b){
    asm volatile("mma.sync.aligned.m16n8k8.row.col.f32.tf32.tf32.f32 "
        "{%0,%1,%2,%3}, {%4,%5,%6,%7}, {%8,%9}, {%0,%1,%2,%3};"
        : "+f"(d[0]), "+f"(d[1]), "+f"(d[2]), "+f"(d[3])
        : "r"(a[0]), "r"(a[1]), "r"(a[2]), "r"(a[3]), "r"(b[0]), "r"(b[1]));
}
__device__ __forceinline__ void mma16(float* d, const uint32_t* a, const uint32_t* b){
    asm volatile("mma.sync.aligned.m16n8k16.row.col.f32.bf16.bf16.f32 "
        "{%0,%1,%2,%3}, {%4,%5,%6,%7}, {%8,%9}, {%0,%1,%2,%3};"
        : "+f"(d[0]), "+f"(d[1]), "+f"(d[2]), "+f"(d[3])
        : "r"(a[0]), "r"(a[1]), "r"(a[2]), "r"(a[3]), "r"(b[0]), "r"(b[1]));
}
__device__ __forceinline__ void ldsm4t(uint32_t& r0, uint32_t& r1, uint32_t& r2, uint32_t& r3,
                                       uint32_t addr){
    asm volatile("ldmatrix.sync.aligned.m8n8.x4.trans.shared.b16 {%0,%1,%2,%3}, [%4];"
        : "=r"(r0), "=r"(r1), "=r"(r2), "=r"(r3) : "r"(addr));
}
__device__ __forceinline__ void ldsm4(uint32_t& r0, uint32_t& r1, uint32_t& r2, uint32_t& r3,
                                      uint32_t addr){
    asm volatile("ldmatrix.sync.aligned.m8n8.x4.shared.b16 {%0,%1,%2,%3}, [%4];"
        : "=r"(r0), "=r"(r1), "=r"(r2), "=r"(r3) : "r"(addr));
}
__device__ __forceinline__ uint32_t smem_u32(const void* p){
    uint32_t a; asm("{ .reg .u64 t; cvta.to.shared.u64 t, %1; cvt.u32.u64 %0, t; }" : "=r"(a) : "l"(p));
    return a;
}
__device__ __forceinline__ void cpa16(uint32_t saddr, const void* g){
    asm volatile("cp.async.ca.shared.global [%0], [%1], 16;" :: "r"(saddr), "l"(g));
}
#define CP_COMMIT() asm volatile("cp.async.commit_group;" ::: "memory")
#define CP_WAIT0()  asm volatile("cp.async.wait_group 0;" ::: "memory")

// ================= tf32 core (k_phi): 256 thr, 128x128, BK=32 =================
#define PA0 36
#define PB  136
#define A_FL (128*PA0)
#define B_FL (32*PB)
#define STAGE_FL (A_FL + B_FL)          // 8960 floats
#define SMEM_DB (2*STAGE_FL*4)          // 71680

__device__ __forceinline__ void math_chunk0(const float* As, const float* Bs, float acc[2][8][4],
                                            int wm, int wn, int g, int c4){
    #pragma unroll
    for (int ks = 0; ks < 4; ks++){
        const int kb = ks*8;
        uint32_t a[2][4], bf[8][2];
        #pragma unroll
        for (int mf = 0; mf < 2; mf++){
            int row = wm*32 + mf*16 + g;
            a[mf][0] = __float_as_uint(As[(row  )*PA0 + kb + c4    ]);
            a[mf][1] = __float_as_uint(As[(row+8)*PA0 + kb + c4    ]);
            a[mf][2] = __float_as_uint(As[(row  )*PA0 + kb + c4 + 4]);
            a[mf][3] = __float_as_uint(As[(row+8)*PA0 + kb + c4 + 4]);
        }
        #pragma unroll
        for (int nf = 0; nf < 8; nf++){
            int ncol = wn*64 + nf*8 + g;
            bf[nf][0] = __float_as_uint(Bs[(kb+c4  )*PB + ncol]);
            bf[nf][1] = __float_as_uint(Bs[(kb+c4+4)*PB + ncol]);
        }
        #pragma unroll
        for (int mf = 0; mf < 2; mf++)
            #pragma unroll
            for (int nf = 0; nf < 8; nf++)
                mma8(acc[mf][nf], a[mf], bf[nf]);
    }
}

__device__ __forceinline__ void stage_async(uint32_t su, int s, const float* A, int lda,
                                            const float* B, int ldb, int ch, int tid){
    uint32_t base = su + (uint32_t)(s*STAGE_FL*4);
    #pragma unroll
    for (int i = 0; i < 4; i++){
        int idx = tid + i*256;
        int m = idx >> 3, kq = idx & 7;
        cpa16(base + (uint32_t)(m*PA0 + kq*4)*4, A + (size_t)m*lda + ch*32 + kq*4);
    }
    uint32_t bbase = base + A_FL*4;
    #pragma unroll
    for (int i = 0; i < 4; i++){
        int idx = tid + i*256;
        int kr = idx >> 5, nq = idx & 31;
        cpa16(bbase + (uint32_t)(kr*PB + nq*4)*4, B + (size_t)(ch*32 + kr)*ldb + nq*4);
    }
    CP_COMMIT();
}

__device__ __forceinline__ void convert_stage(float* sm, int s, int tid){
    float* base = sm + s*STAGE_FL;
    #pragma unroll
    for (int i = 0; i < 4; i++){
        int idx = tid + i*256;
        int m = idx >> 3, kq = idx & 7;
        float4* p = reinterpret_cast<float4*>(base + m*PA0 + kq*4);
        float4 v = *p;
        v.x=t32(v.x); v.y=t32(v.y); v.z=t32(v.z); v.w=t32(v.w);
        *p = v;
    }
    float* bb = base + A_FL;
    #pragma unroll
    for (int i = 0; i < 4; i++){
        int idx = tid + i*256;
        int kr = idx >> 5, nq = idx & 31;
        float4* p = reinterpret_cast<float4*>(bb + kr*PB + nq*4);
        float4 v = *p;
        v.x=t32(v.x); v.y=t32(v.y); v.z=t32(v.z); v.w=t32(v.w);
        *p = v;
    }
}

__device__ __forceinline__ void gemm_async(const float* A, int lda, const float* B, int ldb,
                                           int kchunks, float acc[2][8][4], float* sm, uint32_t su){
    const int tid = threadIdx.x, lane = tid & 31, wid = tid >> 5;
    const int wm = wid & 3, wn = wid >> 2, g = lane >> 2, c4 = lane & 3;
    #pragma unroll
    for (int mf = 0; mf < 2; mf++)
        #pragma unroll
        for (int nf = 0; nf < 8; nf++)
            #pragma unroll
            for (int j = 0; j < 4; j++) acc[mf][nf][j] = 0.f;

    stage_async(su, 0, A, lda, B, ldb, 0, tid);
    for (int ch = 0; ch < kchunks; ch++){
        int cur = ch & 1;
        CP_WAIT0();
        convert_stage(sm, cur, tid);
        __syncthreads();
        if (ch + 1 < kchunks)
            stage_async(su, cur ^ 1, A, lda, B, ldb, ch + 1, tid);
        math_chunk0(sm + cur*STAGE_FL, sm + cur*STAGE_FL + A_FL, acc, wm, wn, g, c4);
    }
    __syncthreads();
}

// ====== k_phi (merged q+k): phi = sigmoid(X @ W + b) -> bf16, fused reductions ======
__global__ __launch_bounds__(256, 2) void k_phi(const float* __restrict__ Q,
                                                const float* __restrict__ K,
                                                const float* __restrict__ Wq,
                                                const float* __restrict__ Wk,
                                                const float* __restrict__ bq,
                                                const float* __restrict__ bk){
    extern __shared__ float sm[];
    uint32_t su = smem_u32(sm);
    const int which = blockIdx.y >> 9;
    const int m0 = (blockIdx.y & 511) * 128, e0 = blockIdx.x * 128;
    const float* X    = which ? K : Q;
    const float* W    = which ? Wk : Wq;
    const float* bias = which ? bk : bq;
    unsigned short* out = which ? g_phik : g_phiq;
    float acc[2][8][4];
    gemm_async(X + (size_t)m0*DD, DD, W + e0, DD, 8, acc, sm, su);

    const int tid = threadIdx.x, lane = tid & 31, wid = tid >> 5;
    const int wm = wid & 3, wn = wid >> 2, g = lane >> 2, c4 = lane & 3;

    float rpart[2][2] = {{0.f,0.f},{0.f,0.f}};
    float cpart[8][2];
    #pragma unroll
    for (int nf = 0; nf < 8; nf++){ cpart[nf][0]=0.f; cpart[nf][1]=0.f; }

    #pragma unroll
    for (int mf = 0; mf < 2; mf++){
        int row = m0 + wm*32 + mf*16 + g;
        #pragma unroll
        for (int nf = 0; nf < 8; nf++){
            int lcol = wn*64 + nf*8 + c4*2;
            float b0 = bias[e0 + lcol], b1 = bias[e0 + lcol + 1];
            float s00 = sigf(acc[mf][nf][0] + b0), s01 = sigf(acc[mf][nf][1] + b1);
            float s10 = sigf(acc[mf][nf][2] + b0), s11 = sigf(acc[mf][nf][3] + b1);
            *reinterpret_cast<uint32_t*>(out + (size_t)row*DD + e0 + lcol)     = pack_bf2(s00, s01);
            *reinterpret_cast<uint32_t*>(out + (size_t)(row+8)*DD + e0 + lcol) = pack_bf2(s10, s11);
            rpart[mf][0] += s00 + s01;
            rpart[mf][1] += s10 + s11;
            cpart[nf][0] += s00 + s10;
            cpart[nf][1] += s01 + s11;
        }
    }
    __syncthreads();

    if (!which){
        #pragma unroll
        for (int mf = 0; mf < 2; mf++)
            #pragma unroll
            for (int h = 0; h < 2; h++){
                rpart[mf][h] += __shfl_xor_sync(0xffffffffu, rpart[mf][h], 1);
                rpart[mf][h] += __shfl_xor_sync(0xffffffffu, rpart[mf][h], 2);
            }
        if (c4 == 0){
            #pragma unroll
            for (int mf = 0; mf < 2; mf++){
                int r = wm*32 + mf*16 + g;
                sm[wn*128 + r]     = rpart[mf][0];
                sm[wn*128 + r + 8] = rpart[mf][1];
            }
        }
        __syncthreads();
        if (tid < 128)
            g_rowpart[(size_t)blockIdx.x*BN_TOT + m0 + tid] = sm[tid] + sm[128 + tid];
    } else {
        #pragma unroll
        for (int nf = 0; nf < 8; nf++)
            #pragma unroll
            for (int h = 0; h < 2; h++){
                cpart[nf][h] += __shfl_xor_sync(0xffffffffu, cpart[nf][h], 4);
                cpart[nf][h] += __shfl_xor_sync(0xffffffffu, cpart[nf][h], 8);
                cpart[nf][h] += __shfl_xor_sync(0xffffffffu, cpart[nf][h], 16);
            }
        if (g == 0){
            #pragma unroll
            for (int nf = 0; nf < 8; nf++){
                int lcol = wn*64 + nf*8 + c4*2;
                sm[wm*128 + lcol]     = cpart[nf][0];
                sm[wm*128 + lcol + 1] = cpart[nf][1];
            }
        }
        __syncthreads();
        if (tid < 128){
            float s = ((sm[tid] + sm[128+tid]) + (sm[256+tid] + sm[384+tid]));
            int b = m0 >> 12, mt = (m0 >> 7) & 31;
            g_colpart2[((b*32 + mt) << 8) + e0 + tid] = s;
        }
    }
}

// ================= k_vcvt: V -> bf16 =================
__global__ __launch_bounds__(256) void k_vcvt(const float* __restrict__ V){
    size_t i8 = ((size_t)blockIdx.x*256 + threadIdx.x)*8;
    float4 a = *reinterpret_cast<const float4*>(V + i8);
    float4 b = *reinterpret_cast<const float4*>(V + i8 + 4);
    uint4 w;
    w.x = pack_bf2(a.x, a.y);
    w.y = pack_bf2(a.z, a.w);
    w.z = pack_bf2(b.x, b.y);
    w.w = pack_bf2(b.z, b.w);
    *reinterpret_cast<uint4*>(g_Vbf + i8) = w;
}

// ================= k_colsum =================
__global__ __launch_bounds__(256) void k_colsum(){
    int idx = blockIdx.x*256 + threadIdx.x;
    int b = idx >> 8, d = idx & 255;
    float s = 0.f;
    #pragma unroll
    for (int mt = 0; mt < 32; mt++) s += g_colpart2[((b*32+mt)<<8) + d];
    g_colsum[idx] = s;
}

// ================= k_kv: bf16 mma16 + ldmatrix + Taylor-exp, bf16 V =============
#define AS_S 8704               // 32*136 bf16 bytes
#define BS_S 8704               // 32*136 bf16 bytes
#define PK_S 8192               // 32*128 bf16 bytes
#define PV_S 8192               // 32*128 bf16 bytes
#define KVB_AS 0
#define KVB_BS (2*AS_S)         // 17408
#define KVB_PK (KVB_BS + 2*BS_S)// 34816
#define KVB_PV (KVB_PK + 2*PK_S)// 51200
#define SMEM_KV (KVB_PV + 2*PV_S)// 67584
#define PA1H 136

__device__ __forceinline__ void kv_stage(uint32_t su, int buf,
                                         const unsigned short* A, const unsigned short* PK,
                                         const unsigned short* PV, size_t roff, int tid, int cq, int rb){
    #pragma unroll
    for (int i = 0; i < 2; i++){
        int idx = tid + i*256;
        int kr = idx >> 4, dq = idx & 15;
        cpa16(su + KVB_AS + (uint32_t)(buf*AS_S + kr*272 + dq*16), A + (roff+kr)*DD + dq*8);
    }
    #pragma unroll
    for (int r = 0; r < 2; r++){
        int kr = rb + r*16;
        cpa16(su + KVB_PK + (uint32_t)(buf*PK_S + kr*256 + cq*16), PK + (roff+kr)*DD + cq*8);
        cpa16(su + KVB_PV + (uint32_t)(buf*PV_S + kr*256 + cq*16), PV + (roff+kr)*DD + cq*8);
    }
    CP_COMMIT();
}

__global__ __launch_bounds__(256, 2) void k_kv(){
    extern __shared__ char smc[];
    uint32_t su = smem_u32(smc);
    __shared__ float cinvs[128];
    __shared__ float zsm[16*128];
    const int tid = threadIdx.x, lane = tid & 31, wid = tid >> 5;
    const int wm = wid & 3, wn = wid >> 2, g = lane >> 2, c4 = lane & 3;
    const int e0 = blockIdx.x * 128, d0 = blockIdx.y * 128;
    const int b = blockIdx.z >> 2, ks = blockIdx.z & 3;
    const unsigned short* A  = g_phik + (size_t)(b*NN + ks*1024)*DD + d0;
    const unsigned short* PK = g_phik + (size_t)(b*NN + ks*1024)*DD + e0;
    const unsigned short* PV = g_Vbf  + (size_t)(b*NN + ks*1024)*DD + e0;

    if (tid < 128) cinvs[tid] = 1.0f/(g_colsum[b*DD + e0 + tid] + EPSF);

    float acc[2][8][4];
    #pragma unroll
    for (int mf = 0; mf < 2; mf++)
        #pragma unroll
        for (int nf = 0; nf < 8; nf++)
            #pragma unroll
            for (int j = 0; j < 4; j++) acc[mf][nf][j] = 0.f;

    const int cq = tid & 15;     // 8-col group
    const int rb = tid >> 4;     // rows rb, rb+16
    float z[8] = {0.f,0.f,0.f,0.f,0.f,0.f,0.f,0.f};

    // ldmatrix per-lane address components
    const int akrow = (lane & 7) + ((lane & 16) >> 1);   // A: k row within chunk
    const int amcol = (lane & 8);                        // A: m col offset
    const int bkrow = (lane & 7) + (lane & 8);           // B: k row within chunk
    const int bncol = ((lane & 16) >> 1);                // B: n col offset

    kv_stage(su, 0, A, PK, PV, 0, tid, cq, rb);
    __syncthreads();
    float ci[8];
    #pragma unroll
    for (int j = 0; j < 8; j++) ci[j] = cinvs[cq*8 + j];

    for (int ch = 0; ch < 32; ch++){
        const int cur = ch & 1;
        CP_WAIT0();
        // exp phase (Taylor: |s|<~0.01 so 1+s+s^2/2 is exact to ~1e-8): own-staged bytes only
        {
            char* pkb = smc + KVB_PK + cur*PK_S;
            char* pvb = smc + KVB_PV + cur*PV_S;
            char* bsb = smc + KVB_BS + cur*BS_S;
            #pragma unroll
            for (int r = 0; r < 2; r++){
                int kr = rb + r*16;
                uint4 pw = *reinterpret_cast<uint4*>(pkb + kr*256 + cq*16);
                uint4 vw = *reinterpret_cast<uint4*>(pvb + kr*256 + cq*16);
                float p0 = __uint_as_float(pw.x << 16), p1 = __uint_as_float(pw.x & 0xFFFF0000u);
                float p2 = __uint_as_float(pw.y << 16), p3 = __uint_as_float(pw.y & 0xFFFF0000u);
                float p4 = __uint_as_float(pw.z << 16), p5 = __uint_as_float(pw.z & 0xFFFF0000u);
                float p6 = __uint_as_float(pw.w << 16), p7 = __uint_as_float(pw.w & 0xFFFF0000u);
                float v0 = __uint_as_float(vw.x << 16), v1 = __uint_as_float(vw.x & 0xFFFF0000u);
                float v2 = __uint_as_float(vw.y << 16), v3 = __uint_as_float(vw.y & 0xFFFF0000u);
                float v4 = __uint_as_float(vw.z << 16), v5 = __uint_as_float(vw.z & 0xFFFF0000u);
                float v6 = __uint_as_float(vw.w << 16), v7 = __uint_as_float(vw.w & 0xFFFF0000u);
                float s0 = p0*v0*ci[0], s1 = p1*v1*ci[1];
                float s2 = p2*v2*ci[2], s3 = p3*v3*ci[3];
                float s4 = p4*v4*ci[4], s5 = p5*v5*ci[5];
                float s6 = p6*v6*ci[6], s7 = p7*v7*ci[7];
                float e0_ = 1.f + s0*(1.f + 0.5f*s0);
                float e1_ = 1.f + s1*(1.f + 0.5f*s1);
                float e2_ = 1.f + s2*(1.f + 0.5f*s2);
                float e3_ = 1.f + s3*(1.f + 0.5f*s3);
                float e4_ = 1.f + s4*(1.f + 0.5f*s4);
                float e5_ = 1.f + s5*(1.f + 0.5f*s5);
                float e6_ = 1.f + s6*(1.f + 0.5f*s6);
                float e7_ = 1.f + s7*(1.f + 0.5f*s7);
                z[0]+=e0_; z[1]+=e1_; z[2]+=e2_; z[3]+=e3_;
                z[4]+=e4_; z[5]+=e5_; z[6]+=e6_; z[7]+=e7_;
                uint4 w;
                w.x = pack_bf2(e0_, e1_);
                w.y = pack_bf2(e2_, e3_);
                w.z = pack_bf2(e4_, e5_);
                w.w = pack_bf2(e6_, e7_);
                *reinterpret_cast<uint4*>(bsb + kr*272 + cq*16) = w;
            }
        }
        __syncthreads();
        if (ch + 1 < 32)
            kv_stage(su, cur ^ 1, A, PK, PV, (size_t)(ch + 1)*32, tid, cq, rb);
        // math: bf16 mma16, frags via ldmatrix.x4.trans
        {
            uint32_t abase = su + KVB_AS + (uint32_t)(cur*AS_S);
            uint32_t bbase = su + KVB_BS + (uint32_t)(cur*BS_S);
            #pragma unroll
            for (int ks2 = 0; ks2 < 2; ks2++){
                const int kb = ks2*16;
                uint32_t a[2][4];
                #pragma unroll
                for (int mf = 0; mf < 2; mf++){
                    uint32_t ad = abase + (uint32_t)((kb + akrow)*PA1H + wm*32 + mf*16 + amcol)*2;
                    ldsm4t(a[mf][0], a[mf][1], a[mf][2], a[mf][3], ad);
                }
                #pragma unroll
                for (int nf2 = 0; nf2 < 4; nf2++){
                    uint32_t r0, r1, r2, r3;
                    uint32_t bd = bbase + (uint32_t)((kb + bkrow)*PB + wn*64 + nf2*16 + bncol)*2;
                    ldsm4t(r0, r1, r2, r3, bd);
                    uint32_t b0[2] = { r0, r1 };
                    uint32_t b1[2] = { r2, r3 };
                    #pragma unroll
                    for (int mf = 0; mf < 2; mf++){
                        mma16(acc[mf][nf2*2 + 0], a[mf], b0);
                        mma16(acc[mf][nf2*2 + 1], a[mf], b1);
                    }
                }
            }
        }
    }

    __syncthreads();
    #pragma unroll
    for (int j = 0; j < 8; j++) zsm[rb*128 + cq*8 + j] = z[j];
    __syncthreads();
    if (blockIdx.y == 0 && tid < 128){
        float Z = 0.f;
        #pragma unroll
        for (int w = 0; w < 16; w++) Z += zsm[w*128 + tid];
        g_zpart[(b*4 + ks)*DD + e0 + tid] = Z;
    }

    float* part = g_kvpart + (size_t)(ks*BB + b)*DD*DD;
    #pragma unroll
    for (int mf = 0; mf < 2; mf++){
        int row = d0 + wm*32 + mf*16 + g;
        #pragma unroll
        for (int nf = 0; nf < 8; nf++){
            int col = e0 + wn*64 + nf*8 + c4*2;
            float2 r0 = { acc[mf][nf][0], acc[mf][nf][1] };
            float2 r1 = { acc[mf][nf][2], acc[mf][nf][3] };
            *reinterpret_cast<float2*>(part + (size_t)row*DD + col)     = r0;
            *reinterpret_cast<float2*>(part + (size_t)(row+8)*DD + col) = r1;
        }
    }
}

// ============ k_kvscaleT: kvT[e][d] = bf16( (Σ ks parts[d][e]) / Z[e] ) ============
__global__ __launch_bounds__(256) void k_kvscaleT(){
    __shared__ float t[32][33];
    __shared__ float zc[32];
    const int d0 = blockIdx.x*32, e0t = blockIdx.y*32, b = blockIdx.z;
    const int tx = threadIdx.x & 31, ty = threadIdx.x >> 5;
    const size_t S = (size_t)BB*DD*DD;
    if (ty == 0){
        int zb = b*4*DD + e0t + tx;
        zc[tx] = ((g_zpart[zb] + g_zpart[zb+DD]) + (g_zpart[zb+2*DD] + g_zpart[zb+3*DD]));
    }
    for (int i = ty; i < 32; i += 8){
        size_t idx = (size_t)b*DD*DD + (size_t)(d0+i)*DD + e0t + tx;
        t[i][tx] = ((g_kvpart[idx] + g_kvpart[idx+S]) + (g_kvpart[idx+2*S] + g_kvpart[idx+3*S]));
    }
    __syncthreads();
    unsigned short* o = g_kvT + (size_t)b*DD*DD;
    for (int i = ty; i < 32; i += 8){
        float v = t[tx][i] / zc[i];
        unsigned short h; asm("cvt.rn.bf16.f32 %0, %1;" : "=h"(h) : "f"(v));
        o[(size_t)(e0t+i)*DD + d0 + tx] = h;
    }
}

// ================= k_out: bf16 m16n8k16 + ldmatrix, R = gate * (phi_q @ KV) =======
#define PAOH 56                 // halfs pad (112B rows)
#define OA_S (128*PAOH*2)       // 14336
#define OB_S (128*PAOH*2)
#define OUT_STAGE (OA_S + OB_S) // 28672
#define SMEM_OUT (2*OUT_STAGE)  // 57344

__device__ __forceinline__ void out_stage(uint32_t su, int buf, const unsigned short* A,
                                          const unsigned short* B, int ch, int tid){
    uint32_t base = su + (uint32_t)(buf*OUT_STAGE);
    #pragma unroll
    for (int i = 0; i < 2; i++){
        int idx = tid + i*256;
        int m = idx >> 2, kq = idx & 3;
        cpa16(base + (uint32_t)(m*112 + kq*16), A + (size_t)m*DD + ch*32 + kq*8);
    }
    uint32_t bbase = base + OA_S;
    #pragma unroll
    for (int i = 0; i < 2; i++){
        int idx = tid + i*256;
        int n = idx >> 2, kq = idx & 3;
        cpa16(bbase + (uint32_t)(n*112 + kq*16), B + (size_t)n*DD + ch*32 + kq*8);
    }
    CP_COMMIT();
}

__global__ __launch_bounds__(256, 2) void k_out(float* __restrict__ out){
    extern __shared__ char smc[];
    uint32_t su = smem_u32(smc);
    const int m0 = blockIdx.y * 128, e0 = blockIdx.x * 128;
    const int b = m0 >> 12;
    const unsigned short* A = g_phiq + (size_t)m0*DD;
    const unsigned short* B = g_kvT + (size_t)b*DD*DD + (size_t)e0*DD;
    const int tid = threadIdx.x, lane = tid & 31, wid = tid >> 5;
    const int wm = wid & 3, wn = wid >> 2, g = lane >> 2, c4 = lane & 3;

    // ldmatrix (non-trans) per-lane address components
    const int aorow = lane & 15;                 // A row offset
    const int aok   = (lane >> 4) * 8;           // A k offset
    const int borow = (lane & 7) + ((lane >> 4) << 3);   // B n-row offset
    const int bok   = ((lane >> 3) & 1) * 8;             // B k offset

    float acc[2][8][4];
    #pragma unroll
    for (int mf = 0; mf < 2; mf++)
        #pragma unroll
        for (int nf = 0; nf < 8; nf++)
            #pragma unroll
            for (int j = 0; j < 4; j++) acc[mf][nf][j] = 0.f;

    out_stage(su, 0, A, B, 0, tid);
    for (int ch = 0; ch < 8; ch++){
        const int cur = ch & 1;
        CP_WAIT0();
        __syncthreads();
        if (ch + 1 < 8) out_stage(su, cur ^ 1, A, B, ch + 1, tid);
        uint32_t abase = su + (uint32_t)(cur*OUT_STAGE);
        uint32_t bbase = abase + OA_S;
        #pragma unroll
        for (int ks2 = 0; ks2 < 2; ks2++){
            const int kb = ks2*16;
            uint32_t a[2][4];
            #pragma unroll
            for (int mf = 0; mf < 2; mf++){
                uint32_t ad = abase + (uint32_t)((wm*32 + mf*16 + aorow)*112 + (kb + aok)*2);
                ldsm4(a[mf][0], a[mf][1], a[mf][2], a[mf][3], ad);
            }
            #pragma unroll
            for (int nf2 = 0; nf2 < 4; nf2++){
                uint32_t r0, r1, r2, r3;
                uint32_t bd = bbase + (uint32_t)((wn*64 + nf2*16 + borow)*112 + (kb + bok)*2);
                ldsm4(r0, r1, r2, r3, bd);
                uint32_t b0[2] = { r0, r1 };
                uint32_t b1[2] = { r2, r3 };
                #pragma unroll
                for (int mf = 0; mf < 2; mf++){
                    mma16(acc[mf][nf2*2 + 0], a[mf], b0);
                    mma16(acc[mf][nf2*2 + 1], a[mf], b1);
                }
            }
        }
    }

    #pragma unroll
    for (int mf = 0; mf < 2; mf++){
        int row = m0 + wm*32 + mf*16 + g;
        float rs0 = g_rowpart[row]   + g_rowpart[BN_TOT + row];
        float rs1 = g_rowpart[row+8] + g_rowpart[BN_TOT + row + 8];
        float sc0 = sigf(rs0) / (rs0 + EPSF);
        float sc1 = sigf(rs1) / (rs1 + EPSF);
        #pragma unroll
        for (int nf = 0; nf < 8; nf++){
            int col = e0 + wn*64 + nf*8 + c4*2;
            float2 r0 = { acc[mf][nf][0]*sc0, acc[mf][nf][1]*sc0 };
            float2 r1 = { acc[mf][nf][2]*sc1, acc[mf][nf][3]*sc1 };
            *reinterpret_cast<float2*>(out + (size_t)row*DD + col)     = r0;
            *reinterpret_cast<float2*>(out + (size_t)(row+8)*DD + col) = r1;
        }
    }
}

// ================= launch =================
extern "C" void kernel_launch(void* const* d_in, const int* in_sizes, int n_in,
                              void* d_out, int out_size){
    const float* Q  = (const float*)d_in[0];
    const float* K  = (const float*)d_in[1];
    const float* V  = (const float*)d_in[2];
    const float* Wq = (const float*)d_in[3];
    const float* bq = (const float*)d_in[4];
    const float* Wk = (const float*)d_in[5];
    const float* bk = (const float*)d_in[6];
    float* out = (float*)d_out;
    (void)in_sizes; (void)n_in; (void)out_size;

    cudaFuncSetAttribute(k_phi, cudaFuncAttributeMaxDynamicSharedMemorySize, SMEM_DB);
    cudaFuncSetAttribute(k_kv,  cudaFuncAttributeMaxDynamicSharedMemorySize, SMEM_KV);
    cudaFuncSetAttribute(k_out, cudaFuncAttributeMaxDynamicSharedMemorySize, SMEM_OUT);

    k_vcvt<<<BN_TOT*DD/8/256, 256>>>(V);                  // V -> bf16
    k_phi<<<dim3(2,1024), 256, SMEM_DB>>>(Q, K, Wq, Wk, bq, bk);  // merged phi_q + phi_k
    k_colsum<<<16, 256>>>();
    k_kv<<<dim3(2,2,BB*4), 256, SMEM_KV>>>();             // KV' partials + Z (bf16 mma)
    k_kvscaleT<<<dim3(8,8,BB), 256>>>();                  // combine, /Z, transpose -> bf16
    k_out<<<dim3(2,512), 256, SMEM_OUT>>>(out);           // final R (bf16 MMA)
}

// round 17
// speedup vs baseline: 1.9716x; 1.1853x over previous
#include <cuda_runtime.h>
#include <cstdint>

#define BB 16
#define NN 4096
#define DD 256
#define BN_TOT (BB*NN)          // 65536
#define EPSF 1e-6f

// ---------------- scratch ----------------
__device__ unsigned short g_phiq[BN_TOT*DD];   // [bn][d] bf16, 32MB
__device__ unsigned short g_phik[BN_TOT*DD];   // [bn][d] bf16, 32MB
__device__ unsigned short g_Vbf [BN_TOT*DD];   // [bn][d] bf16, 32MB
__device__ float g_rowpart[2*BN_TOT];
__device__ float g_colpart2[BB*32*DD];
__device__ float g_colsum[BB*DD];
__device__ float g_zpart[BB*4*DD];             // Z partials per ks (4)
__device__ float g_kvpart[4*BB*DD*DD];         // split-K KV partials [d][e]
__device__ unsigned short g_kvT[BB*DD*DD];     // bf16, TRANSPOSED [b][e][d]

__device__ __forceinline__ float sigf(float x){ return 1.0f/(1.0f + __expf(-x)); }
__device__ __forceinline__ uint32_t pack_bf2(float lo, float hi){
    uint32_t r; asm("cvt.rn.bf16x2.f32 %0, %1, %2;" : "=r"(r) : "f"(hi), "f"(lo)); return r;
}
__device__ __forceinline__ void mma16(float* d, const uint32_t* a, const uint32_t* b){
    asm volatile("mma.sync.aligned.m16n8k16.row.col.f32.bf16.bf16.f32 "
        "{%0,%1,%2,%3}, {%4,%5,%6,%7}, {%8,%9}, {%0,%1,%2,%3};"
        : "+f"(d[0]), "+f"(d[1]), "+f"(d[2]), "+f"(d[3])
        : "r"(a[0]), "r"(a[1]), "r"(a[2]), "r"(a[3]), "r"(b[0]), "r"(b[1]));
}
__device__ __forceinline__ void ldsm4t(uint32_t& r0, uint32_t& r1, uint32_t& r2, uint32_t& r3,
                                       uint32_t addr){
    asm volatile("ldmatrix.sync.aligned.m8n8.x4.trans.shared.b16 {%0,%1,%2,%3}, [%4];"
        : "=r"(r0), "=r"(r1), "=r"(r2), "=r"(r3) : "r"(addr));
}
__device__ __forceinline__ void ldsm4(uint32_t& r0, uint32_t& r1, uint32_t& r2, uint32_t& r3,
                                      uint32_t addr){
    asm volatile("ldmatrix.sync.aligned.m8n8.x4.shared.b16 {%0,%1,%2,%3}, [%4];"
        : "=r"(r0), "=r"(r1), "=r"(r2), "=r"(r3) : "r"(addr));
}
__device__ __forceinline__ uint32_t smem_u32(const void* p){
    uint32_t a; asm("{ .reg .u64 t; cvta.to.shared.u64 t, %1; cvt.u32.u64 %0, t; }" : "=r"(a) : "l"(p));
    return a;
}
__device__ __forceinline__ void cpa16(uint32_t saddr, const void* g){
    asm volatile("cp.async.ca.shared.global [%0], [%1], 16;" :: "r"(saddr), "l"(g));
}
#define CP_COMMIT() asm volatile("cp.async.commit_group;" ::: "memory")
#define CP_WAIT0()  asm volatile("cp.async.wait_group 0;" ::: "memory")

// ================= k_phi: bf16 mma16 core, 256 thr, 128x128, BK=32 =================
// fp32 scratch pitches (floats)
#define PA0 36
#define PB  136
// bf16 operand pitches (halfs)
#define PAQ 56                  // A [m][k], 112 B rows
#define PBQ 136                 // B [k][n], 272 B rows
#define QA_SCR 0                // fp32 A scratch 128*36*4 = 18432
#define QB_SCR 18432            // fp32 B scratch 32*136*4 = 17408
#define QBF_A  35840            // bf16 A dbl buf: 2 x 128*112 = 2*14336
#define QBF_B  (QBF_A + 2*14336)// 64512; bf16 B dbl buf: 2 x 32*272 = 2*8704
#define SMEM_PHI (QBF_B + 2*8704) // 81920

__device__ __forceinline__ void stage_phi(uint32_t su, const float* A,
                                          const float* B, int ch, int tid){
    #pragma unroll
    for (int i = 0; i < 4; i++){
        int idx = tid + i*256;
        int m = idx >> 3, kq = idx & 7;
        cpa16(su + QA_SCR + (uint32_t)(m*PA0 + kq*4)*4, A + (size_t)m*DD + ch*32 + kq*4);
    }
    #pragma unroll
    for (int i = 0; i < 4; i++){
        int idx = tid + i*256;
        int kr = idx >> 5, nq = idx & 31;
        cpa16(su + QB_SCR + (uint32_t)(kr*PB + nq*4)*4, B + (size_t)(ch*32 + kr)*DD + nq*4);
    }
    CP_COMMIT();
}

__device__ __forceinline__ void convert_phi(char* smc, int buf, int tid){
    const float* sa = reinterpret_cast<const float*>(smc + QA_SCR);
    const float* sb = reinterpret_cast<const float*>(smc + QB_SCR);
    char* da = smc + QBF_A + buf*14336;
    char* db = smc + QBF_B + buf*8704;
    #pragma unroll
    for (int i = 0; i < 4; i++){
        int idx = tid + i*256;
        int m = idx >> 3, kq = idx & 7;
        float4 v = *reinterpret_cast<const float4*>(sa + m*PA0 + kq*4);
        uint2 w = { pack_bf2(v.x, v.y), pack_bf2(v.z, v.w) };
        *reinterpret_cast<uint2*>(da + m*112 + kq*8) = w;
    }
    #pragma unroll
    for (int i = 0; i < 4; i++){
        int idx = tid + i*256;
        int kr = idx >> 5, nq = idx & 31;
        float4 v = *reinterpret_cast<const float4*>(sb + kr*PB + nq*4);
        uint2 w = { pack_bf2(v.x, v.y), pack_bf2(v.z, v.w) };
        *reinterpret_cast<uint2*>(db + kr*272 + nq*8) = w;
    }
}

// ====== k_phi (merged q+k): phi = sigmoid(X @ W + b) -> bf16, fused reductions
//        which==1 CTAs also convert their V tile to bf16 (replaces k_vcvt) ======
__global__ __launch_bounds__(256, 2) void k_phi(const float* __restrict__ Q,
                                                const float* __restrict__ K,
                                                const float* __restrict__ V,
                                                const float* __restrict__ Wq,
                                                const float* __restrict__ Wk,
                                                const float* __restrict__ bq,
                                                const float* __restrict__ bk){
    extern __shared__ char smc[];
    float* smf = reinterpret_cast<float*>(smc);
    uint32_t su = smem_u32(smc);
    const int which = blockIdx.y >> 9;
    const int m0 = (blockIdx.y & 511) * 128, e0 = blockIdx.x * 128;
    const float* X    = which ? K : Q;
    const float* W    = which ? Wk : Wq;
    const float* bias = which ? bk : bq;
    unsigned short* out = which ? g_phik : g_phiq;
    const int tid = threadIdx.x, lane = tid & 31, wid = tid >> 5;
    const int wm = wid & 3, wn = wid >> 2, g = lane >> 2, c4 = lane & 3;

    // ldmatrix lane mappings (A non-trans per k_out; B trans per k_kv)
    const int aorow = lane & 15, aok = (lane >> 4)*8;
    const int bkrow = (lane & 7) + (lane & 8), bncol = (lane & 16) >> 1;

    float acc[2][8][4];
    #pragma unroll
    for (int mf = 0; mf < 2; mf++)
        #pragma unroll
        for (int nf = 0; nf < 8; nf++)
            #pragma unroll
            for (int j = 0; j < 4; j++) acc[mf][nf][j] = 0.f;

    const float* Ap = X + (size_t)m0*DD;
    const float* Bp = W + e0;
    stage_phi(su, Ap, Bp, 0, tid);
    for (int ch = 0; ch < 8; ch++){
        const int cur = ch & 1;
        CP_WAIT0();
        convert_phi(smc, cur, tid);    // own-staged bytes only
        __syncthreads();
        if (ch + 1 < 8) stage_phi(su, Ap, Bp, ch + 1, tid);
        uint32_t abase = su + QBF_A + (uint32_t)(cur*14336);
        uint32_t bbase = su + QBF_B + (uint32_t)(cur*8704);
        #pragma unroll
        for (int ks2 = 0; ks2 < 2; ks2++){
            const int kb = ks2*16;
            uint32_t a[2][4];
            #pragma unroll
            for (int mf = 0; mf < 2; mf++){
                uint32_t ad = abase + (uint32_t)((wm*32 + mf*16 + aorow)*112 + (kb + aok)*2);
                ldsm4(a[mf][0], a[mf][1], a[mf][2], a[mf][3], ad);
            }
            #pragma unroll
            for (int nf2 = 0; nf2 < 4; nf2++){
                uint32_t r0, r1, r2, r3;
                uint32_t bd = bbase + (uint32_t)((kb + bkrow)*PBQ + wn*64 + nf2*16 + bncol)*2;
                ldsm4t(r0, r1, r2, r3, bd);
                uint32_t b0[2] = { r0, r1 };
                uint32_t b1[2] = { r2, r3 };
                #pragma unroll
                for (int mf = 0; mf < 2; mf++){
                    mma16(acc[mf][nf2*2 + 0], a[mf], b0);
                    mma16(acc[mf][nf2*2 + 1], a[mf], b1);
                }
            }
        }
    }

    float rpart[2][2] = {{0.f,0.f},{0.f,0.f}};
    float cpart[8][2];
    #pragma unroll
    for (int nf = 0; nf < 8; nf++){ cpart[nf][0]=0.f; cpart[nf][1]=0.f; }

    #pragma unroll
    for (int mf = 0; mf < 2; mf++){
        int row = m0 + wm*32 + mf*16 + g;
        #pragma unroll
        for (int nf = 0; nf < 8; nf++){
            int lcol = wn*64 + nf*8 + c4*2;
            float b0 = bias[e0 + lcol], b1 = bias[e0 + lcol + 1];
            float s00 = sigf(acc[mf][nf][0] + b0), s01 = sigf(acc[mf][nf][1] + b1);
            float s10 = sigf(acc[mf][nf][2] + b0), s11 = sigf(acc[mf][nf][3] + b1);
            *reinterpret_cast<uint32_t*>(out + (size_t)row*DD + e0 + lcol)     = pack_bf2(s00, s01);
            *reinterpret_cast<uint32_t*>(out + (size_t)(row+8)*DD + e0 + lcol) = pack_bf2(s10, s11);
            rpart[mf][0] += s00 + s01;
            rpart[mf][1] += s10 + s11;
            cpart[nf][0] += s00 + s10;
            cpart[nf][1] += s01 + s11;
        }
    }
    __syncthreads();   // staging buffers free; reuse smem for reductions

    if (!which){
        #pragma unroll
        for (int mf = 0; mf < 2; mf++)
            #pragma unroll
            for (int h = 0; h < 2; h++){
                rpart[mf][h] += __shfl_xor_sync(0xffffffffu, rpart[mf][h], 1);
                rpart[mf][h] += __shfl_xor_sync(0xffffffffu, rpart[mf][h], 2);
            }
        if (c4 == 0){
            #pragma unroll
            for (int mf = 0; mf < 2; mf++){
                int r = wm*32 + mf*16 + g;
                smf[wn*128 + r]     = rpart[mf][0];
                smf[wn*128 + r + 8] = rpart[mf][1];
            }
        }
        __syncthreads();
        if (tid < 128)
            g_rowpart[(size_t)blockIdx.x*BN_TOT + m0 + tid] = smf[tid] + smf[128 + tid];
    } else {
        #pragma unroll
        for (int nf = 0; nf < 8; nf++)
            #pragma unroll
            for (int h = 0; h < 2; h++){
                cpart[nf][h] += __shfl_xor_sync(0xffffffffu, cpart[nf][h], 4);
                cpart[nf][h] += __shfl_xor_sync(0xffffffffu, cpart[nf][h], 8);
                cpart[nf][h] += __shfl_xor_sync(0xffffffffu, cpart[nf][h], 16);
            }
        if (g == 0){
            #pragma unroll
            for (int nf = 0; nf < 8; nf++){
                int lcol = wn*64 + nf*8 + c4*2;
                smf[wm*128 + lcol]     = cpart[nf][0];
                smf[wm*128 + lcol + 1] = cpart[nf][1];
            }
        }
        __syncthreads();
        if (tid < 128){
            float s = ((smf[tid] + smf[128+tid]) + (smf[256+tid] + smf[384+tid]));
            int b = m0 >> 12, mt = (m0 >> 7) & 31;
            g_colpart2[((b*32 + mt) << 8) + e0 + tid] = s;
        }
        // fused V -> bf16 for this (m-tile, e-tile): covers [bn][d] exactly once
        const float* Vp = V + (size_t)m0*DD + e0;
        unsigned short* Vo = g_Vbf + (size_t)m0*DD + e0;
        #pragma unroll
        for (int i = tid; i < 128*32; i += 256){
            int r = i >> 5, c = (i & 31)*4;
            float4 v = *reinterpret_cast<const float4*>(Vp + (size_t)r*DD + c);
            uint2 w = { pack_bf2(v.x, v.y), pack_bf2(v.z, v.w) };
            *reinterpret_cast<uint2*>(Vo + (size_t)r*DD + c) = w;
        }
    }
}

// ================= k_colsum =================
__global__ __launch_bounds__(256) void k_colsum(){
    int idx = blockIdx.x*256 + threadIdx.x;
    int b = idx >> 8, d = idx & 255;
    float s = 0.f;
    #pragma unroll
    for (int mt = 0; mt < 32; mt++) s += g_colpart2[((b*32+mt)<<8) + d];
    g_colsum[idx] = s;
}

// ================= k_kv: bf16 mma16 + ldmatrix + Taylor-exp, bf16 V =============
#define AS_S 8704               // 32*136 bf16 bytes
#define BS_S 8704               // 32*136 bf16 bytes
#define PK_S 8192               // 32*128 bf16 bytes
#define PV_S 8192               // 32*128 bf16 bytes
#define KVB_AS 0
#define KVB_BS (2*AS_S)         // 17408
#define KVB_PK (KVB_BS + 2*BS_S)// 34816
#define KVB_PV (KVB_PK + 2*PK_S)// 51200
#define SMEM_KV (KVB_PV + 2*PV_S)// 67584
#define PA1H 136

__device__ __forceinline__ void kv_stage(uint32_t su, int buf,
                                         const unsigned short* A, const unsigned short* PK,
                                         const unsigned short* PV, size_t roff, int tid, int cq, int rb){
    #pragma unroll
    for (int i = 0; i < 2; i++){
        int idx = tid + i*256;
        int kr = idx >> 4, dq = idx & 15;
        cpa16(su + KVB_AS + (uint32_t)(buf*AS_S + kr*272 + dq*16), A + (roff+kr)*DD + dq*8);
    }
    #pragma unroll
    for (int r = 0; r < 2; r++){
        int kr = rb + r*16;
        cpa16(su + KVB_PK + (uint32_t)(buf*PK_S + kr*256 + cq*16), PK + (roff+kr)*DD + cq*8);
        cpa16(su + KVB_PV + (uint32_t)(buf*PV_S + kr*256 + cq*16), PV + (roff+kr)*DD + cq*8);
    }
    CP_COMMIT();
}

__global__ __launch_bounds__(256, 2) void k_kv(){
    extern __shared__ char smc[];
    uint32_t su = smem_u32(smc);
    __shared__ float cinvs[128];
    __shared__ float zsm[16*128];
    const int tid = threadIdx.x, lane = tid & 31, wid = tid >> 5;
    const int wm = wid & 3, wn = wid >> 2, g = lane >> 2, c4 = lane & 3;
    const int e0 = blockIdx.x * 128, d0 = blockIdx.y * 128;
    const int b = blockIdx.z >> 2, ks = blockIdx.z & 3;
    const unsigned short* A  = g_phik + (size_t)(b*NN + ks*1024)*DD + d0;
    const unsigned short* PK = g_phik + (size_t)(b*NN + ks*1024)*DD + e0;
    const unsigned short* PV = g_Vbf  + (size_t)(b*NN + ks*1024)*DD + e0;

    if (tid < 128) cinvs[tid] = 1.0f/(g_colsum[b*DD + e0 + tid] + EPSF);

    float acc[2][8][4];
    #pragma unroll
    for (int mf = 0; mf < 2; mf++)
        #pragma unroll
        for (int nf = 0; nf < 8; nf++)
            #pragma unroll
            for (int j = 0; j < 4; j++) acc[mf][nf][j] = 0.f;

    const int cq = tid & 15;     // 8-col group
    const int rb = tid >> 4;     // rows rb, rb+16
    float z[8] = {0.f,0.f,0.f,0.f,0.f,0.f,0.f,0.f};

    const int akrow = (lane & 7) + ((lane & 16) >> 1);
    const int amcol = (lane & 8);
    const int bkrow = (lane & 7) + (lane & 8);
    const int bncol = ((lane & 16) >> 1);

    kv_stage(su, 0, A, PK, PV, 0, tid, cq, rb);
    __syncthreads();
    float ci[8];
    #pragma unroll
    for (int j = 0; j < 8; j++) ci[j] = cinvs[cq*8 + j];

    for (int ch = 0; ch < 32; ch++){
        const int cur = ch & 1;
        CP_WAIT0();
        {
            char* pkb = smc + KVB_PK + cur*PK_S;
            char* pvb = smc + KVB_PV + cur*PV_S;
            char* bsb = smc + KVB_BS + cur*BS_S;
            #pragma unroll
            for (int r = 0; r < 2; r++){
                int kr = rb + r*16;
                uint4 pw = *reinterpret_cast<uint4*>(pkb + kr*256 + cq*16);
                uint4 vw = *reinterpret_cast<uint4*>(pvb + kr*256 + cq*16);
                float p0 = __uint_as_float(pw.x << 16), p1 = __uint_as_float(pw.x & 0xFFFF0000u);
                float p2 = __uint_as_float(pw.y << 16), p3 = __uint_as_float(pw.y & 0xFFFF0000u);
                float p4 = __uint_as_float(pw.z << 16), p5 = __uint_as_float(pw.z & 0xFFFF0000u);
                float p6 = __uint_as_float(pw.w << 16), p7 = __uint_as_float(pw.w & 0xFFFF0000u);
                float v0 = __uint_as_float(vw.x << 16), v1 = __uint_as_float(vw.x & 0xFFFF0000u);
                float v2 = __uint_as_float(vw.y << 16), v3 = __uint_as_float(vw.y & 0xFFFF0000u);
                float v4 = __uint_as_float(vw.z << 16), v5 = __uint_as_float(vw.z & 0xFFFF0000u);
                float v6 = __uint_as_float(vw.w << 16), v7 = __uint_as_float(vw.w & 0xFFFF0000u);
                float s0 = p0*v0*ci[0], s1 = p1*v1*ci[1];
                float s2 = p2*v2*ci[2], s3 = p3*v3*ci[3];
                float s4 = p4*v4*ci[4], s5 = p5*v5*ci[5];
                float s6 = p6*v6*ci[6], s7 = p7*v7*ci[7];
                float e0_ = 1.f + s0*(1.f + 0.5f*s0);
                float e1_ = 1.f + s1*(1.f + 0.5f*s1);
                float e2_ = 1.f + s2*(1.f + 0.5f*s2);
                float e3_ = 1.f + s3*(1.f + 0.5f*s3);
                float e4_ = 1.f + s4*(1.f + 0.5f*s4);
                float e5_ = 1.f + s5*(1.f + 0.5f*s5);
                float e6_ = 1.f + s6*(1.f + 0.5f*s6);
                float e7_ = 1.f + s7*(1.f + 0.5f*s7);
                z[0]+=e0_; z[1]+=e1_; z[2]+=e2_; z[3]+=e3_;
                z[4]+=e4_; z[5]+=e5_; z[6]+=e6_; z[7]+=e7_;
                uint4 w;
                w.x = pack_bf2(e0_, e1_);
                w.y = pack_bf2(e2_, e3_);
                w.z = pack_bf2(e4_, e5_);
                w.w = pack_bf2(e6_, e7_);
                *reinterpret_cast<uint4*>(bsb + kr*272 + cq*16) = w;
            }
        }
        __syncthreads();
        if (ch + 1 < 32)
            kv_stage(su, cur ^ 1, A, PK, PV, (size_t)(ch + 1)*32, tid, cq, rb);
        {
            uint32_t abase = su + KVB_AS + (uint32_t)(cur*AS_S);
            uint32_t bbase = su + KVB_BS + (uint32_t)(cur*BS_S);
            #pragma unroll
            for (int ks2 = 0; ks2 < 2; ks2++){
                const int kb = ks2*16;
                uint32_t a[2][4];
                #pragma unroll
                for (int mf = 0; mf < 2; mf++){
                    uint32_t ad = abase + (uint32_t)((kb + akrow)*PA1H + wm*32 + mf*16 + amcol)*2;
                    ldsm4t(a[mf][0], a[mf][1], a[mf][2], a[mf][3], ad);
                }
                #pragma unroll
                for (int nf2 = 0; nf2 < 4; nf2++){
                    uint32_t r0, r1, r2, r3;
                    uint32_t bd = bbase + (uint32_t)((kb + bkrow)*PA1H + wn*64 + nf2*16 + bncol)*2;
                    ldsm4t(r0, r1, r2, r3, bd);
                    uint32_t b0[2] = { r0, r1 };
                    uint32_t b1[2] = { r2, r3 };
                    #pragma unroll
                    for (int mf = 0; mf < 2; mf++){
                        mma16(acc[mf][nf2*2 + 0], a[mf], b0);
                        mma16(acc[mf][nf2*2 + 1], a[mf], b1);
                    }
                }
            }
        }
    }

    __syncthreads();
    #pragma unroll
    for (int j = 0; j < 8; j++) zsm[rb*128 + cq*8 + j] = z[j];
    __syncthreads();
    if (blockIdx.y == 0 && tid < 128){
        float Z = 0.f;
        #pragma unroll
        for (int w = 0; w < 16; w++) Z += zsm[w*128 + tid];
        g_zpart[(b*4 + ks)*DD + e0 + tid] = Z;
    }

    float* part = g_kvpart + (size_t)(ks*BB + b)*DD*DD;
    #pragma unroll
    for (int mf = 0; mf < 2; mf++){
        int row = d0 + wm*32 + mf*16 + g;
        #pragma unroll
        for (int nf = 0; nf < 8; nf++){
            int col = e0 + wn*64 + nf*8 + c4*2;
            float2 r0 = { acc[mf][nf][0], acc[mf][nf][1] };
            float2 r1 = { acc[mf][nf][2], acc[mf][nf][3] };
            *reinterpret_cast<float2*>(part + (size_t)row*DD + col)     = r0;
            *reinterpret_cast<float2*>(part + (size_t)(row+8)*DD + col) = r1;
        }
    }
}

// ============ k_kvscaleT: kvT[e][d] = bf16( (Σ ks parts[d][e]) / Z[e] ) ============
__global__ __launch_bounds__(256) void k_kvscaleT(){
    __shared__ float t[32][33];
    __shared__ float zc[32];
    const int d0 = blockIdx.x*32, e0t = blockIdx.y*32, b = blockIdx.z;
    const int tx = threadIdx.x & 31, ty = threadIdx.x >> 5;
    const size_t S = (size_t)BB*DD*DD;
    if (ty == 0){
        int zb = b*4*DD + e0t + tx;
        zc[tx] = ((g_zpart[zb] + g_zpart[zb+DD]) + (g_zpart[zb+2*DD] + g_zpart[zb+3*DD]));
    }
    for (int i = ty; i < 32; i += 8){
        size_t idx = (size_t)b*DD*DD + (size_t)(d0+i)*DD + e0t + tx;
        t[i][tx] = ((g_kvpart[idx] + g_kvpart[idx+S]) + (g_kvpart[idx+2*S] + g_kvpart[idx+3*S]));
    }
    __syncthreads();
    unsigned short* o = g_kvT + (size_t)b*DD*DD;
    for (int i = ty; i < 32; i += 8){
        float v = t[tx][i] / zc[i];
        unsigned short h; asm("cvt.rn.bf16.f32 %0, %1;" : "=h"(h) : "f"(v));
        o[(size_t)(e0t+i)*DD + d0 + tx] = h;
    }
}

// ================= k_out: bf16 m16n8k16 + ldmatrix, R = gate * (phi_q @ KV) =======
#define PAOH 56                 // halfs pad (112B rows)
#define OA_S (128*PAOH*2)       // 14336
#define OB_S (128*PAOH*2)
#define OUT_STAGE (OA_S + OB_S) // 28672
#define SMEM_OUT (2*OUT_STAGE)  // 57344

__device__ __forceinline__ void out_stage(uint32_t su, int buf, const unsigned short* A,
                                          const unsigned short* B, int ch, int tid){
    uint32_t base = su + (uint32_t)(buf*OUT_STAGE);
    #pragma unroll
    for (int i = 0; i < 2; i++){
        int idx = tid + i*256;
        int m = idx >> 2, kq = idx & 3;
        cpa16(base + (uint32_t)(m*112 + kq*16), A + (size_t)m*DD + ch*32 + kq*8);
    }
    uint32_t bbase = base + OA_S;
    #pragma unroll
    for (int i = 0; i < 2; i++){
        int idx = tid + i*256;
        int n = idx >> 2, kq = idx & 3;
        cpa16(bbase + (uint32_t)(n*112 + kq*16), B + (size_t)n*DD + ch*32 + kq*8);
    }
    CP_COMMIT();
}

__global__ __launch_bounds__(256, 2) void k_out(float* __restrict__ out){
    extern __shared__ char smc[];
    uint32_t su = smem_u32(smc);
    const int m0 = blockIdx.y * 128, e0 = blockIdx.x * 128;
    const int b = m0 >> 12;
    const unsigned short* A = g_phiq + (size_t)m0*DD;
    const unsigned short* B = g_kvT + (size_t)b*DD*DD + (size_t)e0*DD;
    const int tid = threadIdx.x, lane = tid & 31, wid = tid >> 5;
    const int wm = wid & 3, wn = wid >> 2, g = lane >> 2, c4 = lane & 3;

    const int aorow = lane & 15;
    const int aok   = (lane >> 4) * 8;
    const int borow = (lane & 7) + ((lane >> 4) << 3);
    const int bok   = ((lane >> 3) & 1) * 8;

    float acc[2][8][4];
    #pragma unroll
    for (int mf = 0; mf < 2; mf++)
        #pragma unroll
        for (int nf = 0; nf < 8; nf++)
            #pragma unroll
            for (int j = 0; j < 4; j++) acc[mf][nf][j] = 0.f;

    out_stage(su, 0, A, B, 0, tid);
    for (int ch = 0; ch < 8; ch++){
        const int cur = ch & 1;
        CP_WAIT0();
        __syncthreads();
        if (ch + 1 < 8) out_stage(su, cur ^ 1, A, B, ch + 1, tid);
        uint32_t abase = su + (uint32_t)(cur*OUT_STAGE);
        uint32_t bbase = abase + OA_S;
        #pragma unroll
        for (int ks2 = 0; ks2 < 2; ks2++){
            const int kb = ks2*16;
            uint32_t a[2][4];
            #pragma unroll
            for (int mf = 0; mf < 2; mf++){
                uint32_t ad = abase + (uint32_t)((wm*32 + mf*16 + aorow)*112 + (kb + aok)*2);
                ldsm4(a[mf][0], a[mf][1], a[mf][2], a[mf][3], ad);
            }
            #pragma unroll
            for (int nf2 = 0; nf2 < 4; nf2++){
                uint32_t r0, r1, r2, r3;
                uint32_t bd = bbase + (uint32_t)((wn*64 + nf2*16 + borow)*112 + (kb + bok)*2);
                ldsm4(r0, r1, r2, r3, bd);
                uint32_t b0[2] = { r0, r1 };
                uint32_t b1[2] = { r2, r3 };
                #pragma unroll
                for (int mf = 0; mf < 2; mf++){
                    mma16(acc[mf][nf2*2 + 0], a[mf], b0);
                    mma16(acc[mf][nf2*2 + 1], a[mf], b1);
                }
            }
        }
    }

    #pragma unroll
    for (int mf = 0; mf < 2; mf++){
        int row = m0 + wm*32 + mf*16 + g;
        float rs0 = g_rowpart[row]   + g_rowpart[BN_TOT + row];
        float rs1 = g_rowpart[row+8] + g_rowpart[BN_TOT + row + 8];
        float sc0 = sigf(rs0) / (rs0 + EPSF);
        float sc1 = sigf(rs1) / (rs1 + EPSF);
        #pragma unroll
        for (int nf = 0; nf < 8; nf++){
            int col = e0 + wn*64 + nf*8 + c4*2;
            float2 r0 = { acc[mf][nf][0]*sc0, acc[mf][nf][1]*sc0 };
            float2 r1 = { acc[mf][nf][2]*sc1, acc[mf][nf][3]*sc1 };
            *reinterpret_cast<float2*>(out + (size_t)row*DD + col)     = r0;
            *reinterpret_cast<float2*>(out + (size_t)(row+8)*DD + col) = r1;
        }
    }
}

// ================= launch =================
extern "C" void kernel_launch(void* const* d_in, const int* in_sizes, int n_in,
                              void* d_out, int out_size){
    const float* Q  = (const float*)d_in[0];
    const float* K  = (const float*)d_in[1];
    const float* V  = (const float*)d_in[2];
    const float* Wq = (const float*)d_in[3];
    const float* bq = (const float*)d_in[4];
    const float* Wk = (const float*)d_in[5];
    const float* bk = (const float*)d_in[6];
    float* out = (float*)d_out;
    (void)in_sizes; (void)n_in; (void)out_size;

    cudaFuncSetAttribute(k_phi, cudaFuncAttributeMaxDynamicSharedMemorySize, SMEM_PHI);
    cudaFuncSetAttribute(k_kv,  cudaFuncAttributeMaxDynamicSharedMemorySize, SMEM_KV);
    cudaFuncSetAttribute(k_out, cudaFuncAttributeMaxDynamicSharedMemorySize, SMEM_OUT);

    k_phi<<<dim3(2,1024), 256, SMEM_PHI>>>(Q, K, V, Wq, Wk, bq, bk); // phi (bf16 mma) + V cvt
    k_colsum<<<16, 256>>>();
    k_kv<<<dim3(2,2,BB*4), 256, SMEM_KV>>>();             // KV' partials + Z (bf16 mma)
    k_kvscaleT<<<dim3(8,8,BB), 256>>>();                  // combine, /Z, transpose -> bf16
    k_out<<<dim3(2,512), 256, SMEM_OUT>>>(out);           // final R (bf16 MMA)
}